// round 1
// baseline (speedup 1.0000x reference)
#include <cuda_runtime.h>
#include <math.h>

#define LF     4095
#define NCH    256
#define NB     4
#define SEQLEN 32768
#define EPSF   1e-5f

// ---------------- scratch (static device globals; no allocation) ----------------
__device__ float g_enc [NB*NCH*LF];
__device__ float g_x   [NB*NCH*LF];
__device__ float g_xn  [NB*NCH*LF];
__device__ float g_m1  [NB*NCH*LF];
__device__ float g_m2  [NB*NCH*LF];
__device__ float g_ker [NB*3*LF];
__device__ float g_part[NB*16*LF];
__device__ float g_wc  [12*3*NCH];   // collapsed involution kernel weights
__device__ float g_bcol[12*3];       // collapsed biases

// ---------------- collapse w2@w1 (+ bias) per (block,p,j) ----------------
__global__ void k_prep(const float* __restrict__ w1, const float* __restrict__ b1,
                       const float* __restrict__ w2, const float* __restrict__ b2)
{
    int bp = blockIdx.x;          // 0..11 = blk*3+p
    int j  = blockIdx.y;          // 0..2
    int c  = threadIdx.x;         // 0..255
    const float* w1p = w1 + (size_t)bp*64*NCH;
    const float* w2p = w2 + ((size_t)bp*3 + j)*64;
    float acc = 0.f;
    #pragma unroll 8
    for (int cr = 0; cr < 64; cr++) acc += w2p[cr] * w1p[(size_t)cr*NCH + c];
    g_wc[((size_t)bp*3 + j)*NCH + c] = acc;
    if (c == 0) {
        const float* b1p = b1 + bp*64;
        float bb = b2[bp*3 + j];
        for (int cr = 0; cr < 64; cr++) bb += w2p[cr]*b1p[cr];
        g_bcol[bp*3 + j] = bb;
    }
}

// ---------------- encoder: two strided conv1d, summed ----------------
__global__ void k_enc(const float* __restrict__ ac, const float* __restrict__ bc,
                      const float* __restrict__ acw, const float* __restrict__ bcw,
                      float* __restrict__ enc)
{
    int b  = blockIdx.y;
    int t0 = blockIdx.x * 32;
    int tx = threadIdx.x, ty = threadIdx.y;
    __shared__ float sa[264], sb[264];
    int base = t0 * 8;
    int tid  = ty*32 + tx;
    for (int i = tid; i < 264; i += 256) {
        int gi = base + i;
        sa[i] = (gi < SEQLEN) ? ac[(size_t)b*SEQLEN + gi] : 0.f;
        sb[i] = (gi < SEQLEN) ? bc[(size_t)b*SEQLEN + gi] : 0.f;
    }
    __syncthreads();
    int t = t0 + tx;
    if (t >= LF) return;
    for (int n = ty; n < NCH; n += 8) {
        float acc = 0.f;
        #pragma unroll
        for (int l = 0; l < 16; l++)
            acc += sa[tx*8 + l]*acw[n*16 + l] + sb[tx*8 + l]*bcw[n*16 + l];
        enc[((size_t)b*NCH + n)*LF + t] = acc;
    }
}

// ---------------- channel layernorm (optional scalar-PReLU on input) ----------------
// block (32 t, 8 cgroup); each thread owns 32 channels for one t.
__global__ void k_ln(const float* __restrict__ in, float* __restrict__ outp,
                     const float* __restrict__ gam, const float* __restrict__ bet,
                     const float* __restrict__ alphaPtr)
{
    int b  = blockIdx.y;
    int t  = blockIdx.x*32 + threadIdx.x;
    int ty = threadIdx.y;
    bool valid = (t < LF);
    bool up = (alphaPtr != nullptr);
    float a = up ? *alphaPtr : 0.f;
    float vals[32];
    float s = 0.f, q = 0.f;
    if (valid) {
        const float* ip = in + (size_t)b*NCH*LF + t;
        #pragma unroll
        for (int i = 0; i < 32; i++) {
            int c = ty*32 + i;
            float v = ip[(size_t)c*LF];
            if (up && v < 0.f) v *= a;
            vals[i] = v; s += v; q += v*v;
        }
    } else {
        #pragma unroll
        for (int i = 0; i < 32; i++) vals[i] = 0.f;
    }
    __shared__ float ss[8][33], sq[8][33];
    ss[ty][threadIdx.x] = s; sq[ty][threadIdx.x] = q;
    __syncthreads();
    if (ty == 0) {
        float S = 0.f, Q = 0.f;
        #pragma unroll
        for (int j = 0; j < 8; j++) { S += ss[j][threadIdx.x]; Q += sq[j][threadIdx.x]; }
        float mu  = S * (1.f/NCH);
        float var = Q * (1.f/NCH) - mu*mu;
        ss[0][threadIdx.x] = mu;
        sq[0][threadIdx.x] = rsqrtf(var + EPSF);
    }
    __syncthreads();
    if (!valid) return;
    float mu = ss[0][threadIdx.x], rs = sq[0][threadIdx.x];
    float* op = outp + (size_t)b*NCH*LF + t;
    #pragma unroll
    for (int i = 0; i < 32; i++) {
        int c = ty*32 + i;
        op[(size_t)c*LF] = (vals[i] - mu)*rs*gam[c] + bet[c];
    }
}

// ---------------- 256x256 pointwise GEMM: out[b,o,t] = sum_c W[o,c] X[b,c,t] + bias
// mode 0: plain;  mode 1: + addsrc;  mode 2: relu(.) * enc  (mask apply)
__global__ __launch_bounds__(256) void k_pw(
        const float* __restrict__ W, const float* __restrict__ bias,
        const float* __restrict__ X, const float* __restrict__ addsrc,
        const float* __restrict__ encp, float* __restrict__ outp, int mode)
{
    const int b  = blockIdx.z;
    const float* Xb = X   + (size_t)b*NCH*LF;
    float*       Ob = outp + (size_t)b*NCH*LF;
    const int t0 = blockIdx.x * 64;
    const int o0 = blockIdx.y * 64;
    __shared__ float As[16][64];
    __shared__ float Bs[16][64];
    const int tid = threadIdx.x;
    const int tx = tid & 15, ty = tid >> 4;
    float acc[4][4];
    #pragma unroll
    for (int i = 0; i < 4; i++)
        #pragma unroll
        for (int j = 0; j < 4; j++) acc[i][j] = 0.f;

    for (int k0 = 0; k0 < NCH; k0 += 16) {
        {   // A tile (weights, transposed into As[k][m]); row-major, 16B aligned
            int m  = tid >> 2;
            int kk = (tid & 3) << 2;
            float4 w4 = *(const float4*)&W[(size_t)(o0 + m)*NCH + k0 + kk];
            As[kk+0][m] = w4.x; As[kk+1][m] = w4.y; As[kk+2][m] = w4.z; As[kk+3][m] = w4.w;
        }
        {   // B tile (activations; LF odd => scalar loads)
            int kk = tid >> 4;
            int nn = (tid & 15) << 2;
            const float* xp = &Xb[(size_t)(k0 + kk)*LF + t0 + nn];
            #pragma unroll
            for (int i = 0; i < 4; i++) {
                int t = t0 + nn + i;
                Bs[kk][nn + i] = (t < LF) ? xp[i] : 0.f;
            }
        }
        __syncthreads();
        #pragma unroll
        for (int kk = 0; kk < 16; kk++) {
            float a0 = As[kk][ty*4+0], a1 = As[kk][ty*4+1];
            float a2 = As[kk][ty*4+2], a3 = As[kk][ty*4+3];
            float b0 = Bs[kk][tx*4+0], b1 = Bs[kk][tx*4+1];
            float b2 = Bs[kk][tx*4+2], b3 = Bs[kk][tx*4+3];
            acc[0][0] += a0*b0; acc[0][1] += a0*b1; acc[0][2] += a0*b2; acc[0][3] += a0*b3;
            acc[1][0] += a1*b0; acc[1][1] += a1*b1; acc[1][2] += a1*b2; acc[1][3] += a1*b3;
            acc[2][0] += a2*b0; acc[2][1] += a2*b1; acc[2][2] += a2*b2; acc[2][3] += a2*b3;
            acc[3][0] += a3*b0; acc[3][1] += a3*b1; acc[3][2] += a3*b2; acc[3][3] += a3*b3;
        }
        __syncthreads();
    }
    #pragma unroll
    for (int i = 0; i < 4; i++) {
        int o = o0 + ty*4 + i;
        float bv = bias[o];
        #pragma unroll
        for (int j = 0; j < 4; j++) {
            int t = t0 + tx*4 + j;
            if (t < LF) {
                float v = acc[i][j] + bv;
                size_t gi = ((size_t)b*NCH + o)*LF + t;
                if (mode == 1)       v += addsrc[gi];
                else if (mode == 2)  v  = fmaxf(v, 0.f) * encp[gi];
                Ob[(size_t)o*LF + t] = v;
            }
        }
    }
}

// ---------------- involution kernel-gen: ker[b,j,t] = Wc[j,:] . m[b,:,t] + bcol[j]
__global__ void k_ker(int bp, const float* __restrict__ m)
{
    __shared__ float sw[3*NCH];
    int b = blockIdx.y;
    const float* wsrc = g_wc + (size_t)bp*3*NCH;
    for (int i = threadIdx.x; i < 3*NCH; i += 128) sw[i] = wsrc[i];
    __syncthreads();
    int t = blockIdx.x*128 + threadIdx.x;
    if (t >= LF) return;
    const float* mb = m + (size_t)b*NCH*LF + t;
    float a0 = g_bcol[bp*3+0], a1 = g_bcol[bp*3+1], a2 = g_bcol[bp*3+2];
    #pragma unroll 4
    for (int c = 0; c < NCH; c++) {
        float v = mb[(size_t)c*LF];
        a0 += sw[c]*v; a1 += sw[NCH + c]*v; a2 += sw[2*NCH + c]*v;
    }
    g_ker[((size_t)b*3 + 0)*LF + t] = a0;
    g_ker[((size_t)b*3 + 1)*LF + t] = a1;
    g_ker[((size_t)b*3 + 2)*LF + t] = a2;
}

// ---------------- involution apply + per-channel PReLU ----------------
__global__ void k_inv(const float* __restrict__ m, const float* __restrict__ aP,
                      float* __restrict__ outp)
{
    int t = blockIdx.x*256 + threadIdx.x;
    int c = blockIdx.y, b = blockIdx.z;
    if (t >= LF) return;
    const float* mb = m + ((size_t)b*NCH + c)*LF;
    const float* kb = g_ker + (size_t)b*3*LF;
    float v = kb[LF + t] * mb[t];
    if (t > 0)      v += kb[t]        * mb[t-1];
    if (t < LF-1)   v += kb[2*LF + t] * mb[t+1];
    float al = aP[c];
    outp[((size_t)b*NCH + c)*LF + t] = (v >= 0.f) ? v : al*v;
}

// ---------------- decoder: per-frame 16-tap projection then overlap-add ----------------
__global__ void k_dpart(const float* __restrict__ masked, const float* __restrict__ dw)
{
    int b = blockIdx.y;
    int t = blockIdx.x*32 + threadIdx.x;
    int l = threadIdx.y;            // 0..15
    if (t >= LF) return;
    const float* mb = masked + (size_t)b*NCH*LF + t;
    float acc = 0.f;
    #pragma unroll 4
    for (int c = 0; c < NCH; c++)
        acc += mb[(size_t)c*LF] * dw[c*16 + l];
    g_part[((size_t)b*16 + l)*LF + t] = acc;
}

__global__ void k_combine(float* __restrict__ outp)
{
    int b = blockIdx.y;
    int s = blockIdx.x*256 + threadIdx.x;
    if (s >= SEQLEN) return;
    int t0 = s >> 3, l = s & 7;
    float v = 0.f;
    if (t0 < LF) v += g_part[((size_t)b*16 + l    )*LF + t0    ];
    if (t0 >= 1) v += g_part[((size_t)b*16 + l + 8)*LF + t0 - 1];
    outp[(size_t)b*SEQLEN + s] = v;
}

// ---------------- driver ----------------
extern "C" void kernel_launch(void* const* d_in, const int* in_sizes, int n_in,
                              void* d_out, int out_size)
{
    (void)in_sizes; (void)n_in; (void)out_size;
    const float* noisy_ac    = (const float*)d_in[0];
    const float* noisy_bc    = (const float*)d_in[1];
    const float* ac_w        = (const float*)d_in[2];
    const float* bc_w        = (const float*)d_in[3];
    const float* me_ln_g     = (const float*)d_in[4];
    const float* me_ln_b     = (const float*)d_in[5];
    const float* me_init_w   = (const float*)d_in[6];
    const float* me_init_b   = (const float*)d_in[7];
    const float* blk_ln_g    = (const float*)d_in[8];
    const float* blk_ln_b    = (const float*)d_in[9];
    const float* blk_act_a   = (const float*)d_in[10];
    const float* inv_w1      = (const float*)d_in[11];
    const float* inv_b1      = (const float*)d_in[12];
    const float* inv_w2      = (const float*)d_in[13];
    const float* inv_b2      = (const float*)d_in[14];
    const float* inv_prelu_a = (const float*)d_in[15];
    const float* skip_w      = (const float*)d_in[16];
    const float* skip_b      = (const float*)d_in[17];
    const float* me_final_w  = (const float*)d_in[18];
    const float* me_final_b  = (const float*)d_in[19];
    const float* dec_w       = (const float*)d_in[20];
    float* out = (float*)d_out;

    float *p_enc, *p_x, *p_xn, *p_m1, *p_m2;
    cudaGetSymbolAddress((void**)&p_enc, g_enc);
    cudaGetSymbolAddress((void**)&p_x,   g_x);
    cudaGetSymbolAddress((void**)&p_xn,  g_xn);
    cudaGetSymbolAddress((void**)&p_m1,  g_m1);
    cudaGetSymbolAddress((void**)&p_m2,  g_m2);

    dim3 lnGrid(128, NB), lnBlk(32, 8);
    dim3 pwGrid(64, 4, NB);

    k_prep<<<dim3(12, 3), 256>>>(inv_w1, inv_b1, inv_w2, inv_b2);
    k_enc <<<dim3(128, NB), dim3(32, 8)>>>(noisy_ac, noisy_bc, ac_w, bc_w, p_enc);
    k_ln  <<<lnGrid, lnBlk>>>(p_enc, p_xn, me_ln_g, me_ln_b, nullptr);
    k_pw  <<<pwGrid, 256>>>(me_init_w, me_init_b, p_xn, nullptr, nullptr, p_x, 0);

    for (int blk = 0; blk < 4; blk++) {
        k_ln<<<lnGrid, lnBlk>>>(p_x, p_xn,
                                blk_ln_g + blk*NCH, blk_ln_b + blk*NCH,
                                blk_act_a + blk);
        // p = 0: xn -> m1
        k_ker<<<dim3(32, NB), 128>>>(blk*3 + 0, p_xn);
        k_inv<<<dim3(16, NCH, NB), 256>>>(p_xn, inv_prelu_a + (blk*3 + 0)*NCH, p_m1);
        // p = 1: m1 -> m2
        k_ker<<<dim3(32, NB), 128>>>(blk*3 + 1, p_m1);
        k_inv<<<dim3(16, NCH, NB), 256>>>(p_m1, inv_prelu_a + (blk*3 + 1)*NCH, p_m2);
        // p = 2: m2 -> m1
        k_ker<<<dim3(32, NB), 128>>>(blk*3 + 2, p_m2);
        k_inv<<<dim3(16, NCH, NB), 256>>>(p_m2, inv_prelu_a + (blk*3 + 2)*NCH, p_m1);
        // x = m1 + skip_w[blk] @ xn + skip_b[blk]
        k_pw<<<pwGrid, 256>>>(skip_w + (size_t)blk*NCH*NCH, skip_b + blk*NCH,
                              p_xn, p_m1, nullptr, p_x, 1);
    }

    // mask = relu(me_final @ x + b);  masked = enc * mask   -> p_xn
    k_pw<<<pwGrid, 256>>>(me_final_w, me_final_b, p_x, nullptr, p_enc, p_xn, 2);
    // decoder
    k_dpart  <<<dim3(128, NB), dim3(32, 16)>>>(p_xn, dec_w);
    k_combine<<<dim3(128, NB), 256>>>(out);
}

// round 2
// speedup vs baseline: 1.4923x; 1.4923x over previous
#include <cuda_runtime.h>
#include <cuda_bf16.h>
#include <stdint.h>
#include <math.h>

#define LF     4095
#define LFP    4096
#define NCH    256
#define NB     4
#define SEQLEN 32768
#define EPSF   1e-5f

// ---------------- scratch (static device globals; no allocation) ----------------
__device__ float g_enc [NB*NCH*LFP + 64];
__device__ float g_x   [NB*NCH*LFP + 64];
__device__ float g_xn  [NB*NCH*LFP + 64];
__device__ float g_m1  [NB*NCH*LFP + 64];
__device__ float g_m2  [NB*NCH*LFP + 64];
__device__ float g_ker [NB*3*LFP  + 64];
__device__ float g_part[NB*16*LFP + 64];
__device__ float g_wc  [12*3*NCH];
__device__ float g_bcol[12*3];

// ---------------- collapse w2@w1 (+ bias) per (block,p,j) ----------------
__global__ void k_prep(const float* __restrict__ w1, const float* __restrict__ b1,
                       const float* __restrict__ w2, const float* __restrict__ b2)
{
    int bp = blockIdx.x;          // 0..11 = blk*3+p
    int j  = blockIdx.y;          // 0..2
    int c  = threadIdx.x;         // 0..255
    const float* w1p = w1 + (size_t)bp*64*NCH;
    const float* w2p = w2 + ((size_t)bp*3 + j)*64;
    float acc = 0.f;
    #pragma unroll 8
    for (int cr = 0; cr < 64; cr++) acc += w2p[cr] * w1p[(size_t)cr*NCH + c];
    g_wc[((size_t)bp*3 + j)*NCH + c] = acc;
    if (c == 0) {
        const float* b1p = b1 + bp*64;
        float bb = b2[bp*3 + j];
        for (int cr = 0; cr < 64; cr++) bb += w2p[cr]*b1p[cr];
        g_bcol[bp*3 + j] = bb;
    }
}

// ---------------- encoder ----------------
__global__ void k_enc(const float* __restrict__ ac, const float* __restrict__ bc,
                      const float* __restrict__ acw, const float* __restrict__ bcw,
                      float* __restrict__ enc)
{
    int b  = blockIdx.y;
    int t0 = blockIdx.x * 32;
    int tx = threadIdx.x, ty = threadIdx.y;
    __shared__ float sa[264], sb[264];
    int base = t0 * 8;
    int tid  = ty*32 + tx;
    for (int i = tid; i < 264; i += 256) {
        int gi = base + i;
        sa[i] = (gi < SEQLEN) ? ac[(size_t)b*SEQLEN + gi] : 0.f;
        sb[i] = (gi < SEQLEN) ? bc[(size_t)b*SEQLEN + gi] : 0.f;
    }
    __syncthreads();
    int t = t0 + tx;
    bool valid = (t < LF);
    for (int n = ty; n < NCH; n += 8) {
        float acc = 0.f;
        #pragma unroll
        for (int l = 0; l < 16; l++)
            acc += sa[tx*8 + l]*acw[n*16 + l] + sb[tx*8 + l]*bcw[n*16 + l];
        enc[((size_t)b*NCH + n)*LFP + t] = valid ? acc : 0.f;
    }
}

// ---------------- channel layernorm (optional scalar-PReLU on input) ----------------
__global__ void k_ln(const float* __restrict__ in, float* __restrict__ outp,
                     const float* __restrict__ gam, const float* __restrict__ bet,
                     const float* __restrict__ alphaPtr)
{
    int b  = blockIdx.y;
    int t  = blockIdx.x*32 + threadIdx.x;
    int ty = threadIdx.y;
    bool valid = (t < LF);
    bool up = (alphaPtr != nullptr);
    float a = up ? *alphaPtr : 0.f;
    float vals[32];
    float s = 0.f, q = 0.f;
    if (valid) {
        const float* ip = in + (size_t)b*NCH*LFP + t;
        #pragma unroll
        for (int i = 0; i < 32; i++) {
            int c = ty*32 + i;
            float v = ip[(size_t)c*LFP];
            if (up && v < 0.f) v *= a;
            vals[i] = v; s += v; q += v*v;
        }
    } else {
        #pragma unroll
        for (int i = 0; i < 32; i++) vals[i] = 0.f;
    }
    __shared__ float ss[8][33], sq[8][33];
    ss[ty][threadIdx.x] = s; sq[ty][threadIdx.x] = q;
    __syncthreads();
    if (ty == 0) {
        float S = 0.f, Q = 0.f;
        #pragma unroll
        for (int j = 0; j < 8; j++) { S += ss[j][threadIdx.x]; Q += sq[j][threadIdx.x]; }
        float mu  = S * (1.f/NCH);
        float var = Q * (1.f/NCH) - mu*mu;
        ss[0][threadIdx.x] = mu;
        sq[0][threadIdx.x] = rsqrtf(var + EPSF);
    }
    __syncthreads();
    float* op = outp + (size_t)b*NCH*LFP + t;
    if (!valid) {
        #pragma unroll
        for (int i = 0; i < 32; i++) op[(size_t)(ty*32 + i)*LFP] = 0.f;
        return;
    }
    float mu = ss[0][threadIdx.x], rs = sq[0][threadIdx.x];
    #pragma unroll
    for (int i = 0; i < 32; i++) {
        int c = ty*32 + i;
        op[(size_t)c*LFP] = (vals[i] - mu)*rs*gam[c] + bet[c];
    }
}

// ---------------- tensor-core pointwise GEMM (bf16x3 split ~ fp32 accuracy) ------
// out[b,o,t] = sum_c W[o,c] X[b,c,t] + bias;  mode 0 plain; 1 +addsrc; 2 relu*enc
#define LDSM4(R, addr)  asm volatile("ldmatrix.sync.aligned.m8n8.x4.shared.b16 {%0,%1,%2,%3}, [%4];" \
    : "=r"(R[0]),"=r"(R[1]),"=r"(R[2]),"=r"(R[3]) : "r"(addr))
#define LDSM4T(R, addr) asm volatile("ldmatrix.sync.aligned.m8n8.x4.trans.shared.b16 {%0,%1,%2,%3}, [%4];" \
    : "=r"(R[0]),"=r"(R[1]),"=r"(R[2]),"=r"(R[3]) : "r"(addr))
#define MMA_BF16(D, A, B0, B1) asm volatile( \
    "mma.sync.aligned.m16n8k16.row.col.f32.bf16.bf16.f32 " \
    "{%0,%1,%2,%3}, {%4,%5,%6,%7}, {%8,%9}, {%0,%1,%2,%3};" \
    : "+f"(D[0]), "+f"(D[1]), "+f"(D[2]), "+f"(D[3]) \
    : "r"(A[0]), "r"(A[1]), "r"(A[2]), "r"(A[3]), "r"(B0), "r"(B1))

__device__ __forceinline__ void splitStore8(const float* v, __nv_bfloat16* hp, __nv_bfloat16* lp)
{
    unsigned hh[4], ll[4];
    #pragma unroll
    for (int i = 0; i < 4; i++) {
        float x0 = v[2*i], x1 = v[2*i+1];
        __nv_bfloat16 h0 = __float2bfloat16(x0), h1 = __float2bfloat16(x1);
        __nv_bfloat16 l0 = __float2bfloat16(x0 - __bfloat162float(h0));
        __nv_bfloat16 l1 = __float2bfloat16(x1 - __bfloat162float(h1));
        hh[i] = ((unsigned)__bfloat16_as_ushort(h1) << 16) | __bfloat16_as_ushort(h0);
        ll[i] = ((unsigned)__bfloat16_as_ushort(l1) << 16) | __bfloat16_as_ushort(l0);
    }
    *(uint4*)hp = make_uint4(hh[0],hh[1],hh[2],hh[3]);
    *(uint4*)lp = make_uint4(ll[0],ll[1],ll[2],ll[3]);
}

__global__ __launch_bounds__(256, 2) void k_pw(
        const float* __restrict__ W, const float* __restrict__ bias,
        const float* __restrict__ X, const float* __restrict__ addsrc,
        const float* __restrict__ encp, float* __restrict__ outp, int mode)
{
    const int b  = blockIdx.z;
    const int t0 = blockIdx.x * 128;
    const int o0 = blockIdx.y * 64;
    const float* Xb = X + (size_t)b*NCH*LFP;

    __shared__ __align__(16) __nv_bfloat16 Ah[64][40];
    __shared__ __align__(16) __nv_bfloat16 Al[64][40];
    __shared__ __align__(16) __nv_bfloat16 Bh[32][136];
    __shared__ __align__(16) __nv_bfloat16 Bl[32][136];

    const int tid  = threadIdx.x;
    const int lane = tid & 31, warp = tid >> 5;
    const int wm = warp & 1, wn = warp >> 1;       // warp tile: (wm*32, wn*32)

    const int ar = tid >> 2, ac = (tid & 3) << 3;  // A stage: row 0..63, col {0,8,16,24}
    const int br = tid >> 3, bc = (tid & 7) << 4;  // B stage: row 0..31, col {0,...,112}

    float aR[8], bR[16];
    {
        const float* wp = &W[(size_t)(o0 + ar)*NCH + ac];
        *(float4*)&aR[0] = *(const float4*)&wp[0];
        *(float4*)&aR[4] = *(const float4*)&wp[4];
        const float* xp = &Xb[(size_t)br*LFP + t0 + bc];
        *(float4*)&bR[0]  = *(const float4*)&xp[0];
        *(float4*)&bR[4]  = *(const float4*)&xp[4];
        *(float4*)&bR[8]  = *(const float4*)&xp[8];
        *(float4*)&bR[12] = *(const float4*)&xp[12];
    }

    float acc[2][4][4];
    #pragma unroll
    for (int i = 0; i < 2; i++)
        #pragma unroll
        for (int j = 0; j < 4; j++)
            #pragma unroll
            for (int r = 0; r < 4; r++) acc[i][j][r] = 0.f;

    #pragma unroll 1
    for (int kt = 0; kt < 8; kt++) {
        splitStore8(aR,    &Ah[ar][ac],    &Al[ar][ac]);
        splitStore8(bR,    &Bh[br][bc],    &Bl[br][bc]);
        splitStore8(bR+8,  &Bh[br][bc+8],  &Bl[br][bc+8]);
        __syncthreads();
        if (kt < 7) {
            int k0 = (kt + 1) * 32;
            const float* wp = &W[(size_t)(o0 + ar)*NCH + k0 + ac];
            *(float4*)&aR[0] = *(const float4*)&wp[0];
            *(float4*)&aR[4] = *(const float4*)&wp[4];
            const float* xp = &Xb[(size_t)(k0 + br)*LFP + t0 + bc];
            *(float4*)&bR[0]  = *(const float4*)&xp[0];
            *(float4*)&bR[4]  = *(const float4*)&xp[4];
            *(float4*)&bR[8]  = *(const float4*)&xp[8];
            *(float4*)&bR[12] = *(const float4*)&xp[12];
        }
        #pragma unroll
        for (int ks = 0; ks < 2; ks++) {
            const int kb = ks * 16;
            unsigned a_hi[2][4], a_lo[2][4], b_hi[2][4], b_lo[2][4];
            #pragma unroll
            for (int mt = 0; mt < 2; mt++) {
                int rowA = wm*32 + mt*16 + (lane & 15);
                int colA = kb + ((lane >> 4) << 3);
                unsigned sa = (unsigned)__cvta_generic_to_shared(&Ah[rowA][colA]);
                LDSM4(a_hi[mt], sa);
                unsigned sl = (unsigned)__cvta_generic_to_shared(&Al[rowA][colA]);
                LDSM4(a_lo[mt], sl);
            }
            #pragma unroll
            for (int ng = 0; ng < 2; ng++) {
                int rowB = kb + (lane & 15);
                int colB = wn*32 + ng*16 + ((lane >> 4) << 3);
                unsigned sb = (unsigned)__cvta_generic_to_shared(&Bh[rowB][colB]);
                LDSM4T(b_hi[ng], sb);
                unsigned sl = (unsigned)__cvta_generic_to_shared(&Bl[rowB][colB]);
                LDSM4T(b_lo[ng], sl);
            }
            #pragma unroll
            for (int mt = 0; mt < 2; mt++)
                #pragma unroll
                for (int ng = 0; ng < 2; ng++)
                    #pragma unroll
                    for (int hf = 0; hf < 2; hf++) {
                        int nt = ng*2 + hf;
                        MMA_BF16(acc[mt][nt], a_hi[mt], b_hi[ng][hf*2], b_hi[ng][hf*2+1]);
                        MMA_BF16(acc[mt][nt], a_hi[mt], b_lo[ng][hf*2], b_lo[ng][hf*2+1]);
                        MMA_BF16(acc[mt][nt], a_lo[mt], b_hi[ng][hf*2], b_hi[ng][hf*2+1]);
                    }
        }
        __syncthreads();
    }

    const int g = lane >> 2, tq = lane & 3;
    const size_t bbase = (size_t)b*NCH*LFP;
    #pragma unroll
    for (int mt = 0; mt < 2; mt++)
        #pragma unroll
        for (int rr = 0; rr < 2; rr++) {
            int o = o0 + wm*32 + mt*16 + rr*8 + g;
            float bv = bias[o];
            size_t rowo = bbase + (size_t)o*LFP;
            #pragma unroll
            for (int nt = 0; nt < 4; nt++)
                #pragma unroll
                for (int cc = 0; cc < 2; cc++) {
                    int t = t0 + wn*32 + nt*8 + tq*2 + cc;
                    float v = acc[mt][nt][rr*2 + cc] + bv;
                    if (mode == 1)      v += addsrc[rowo + t];
                    else if (mode == 2) v  = fmaxf(v, 0.f) * encp[rowo + t];
                    if (t >= LF) v = 0.f;
                    outp[rowo + t] = v;
                }
        }
}

// ---------------- involution kernel-gen ----------------
__global__ void k_ker(int bp, const float* __restrict__ m)
{
    __shared__ float sw[3*NCH];
    int b = blockIdx.y;
    const float* wsrc = g_wc + (size_t)bp*3*NCH;
    for (int i = threadIdx.x; i < 3*NCH; i += 128) sw[i] = wsrc[i];
    __syncthreads();
    int t = blockIdx.x*128 + threadIdx.x;
    float* kout = g_ker + (size_t)b*3*LFP;
    if (t >= LF) {
        kout[t] = 0.f; kout[LFP + t] = 0.f; kout[2*LFP + t] = 0.f;
        return;
    }
    const float* mb = m + (size_t)b*NCH*LFP + t;
    float a0 = g_bcol[bp*3+0], a1 = g_bcol[bp*3+1], a2 = g_bcol[bp*3+2];
    #pragma unroll 4
    for (int c = 0; c < NCH; c++) {
        float v = mb[(size_t)c*LFP];
        a0 += sw[c]*v; a1 += sw[NCH + c]*v; a2 += sw[2*NCH + c]*v;
    }
    kout[t] = a0; kout[LFP + t] = a1; kout[2*LFP + t] = a2;
}

// ---------------- involution apply + per-channel PReLU (vectorized 4t) ----------------
__global__ void k_inv(const float* __restrict__ m, const float* __restrict__ aP,
                      float* __restrict__ outp)
{
    int t = (blockIdx.x*256 + threadIdx.x) * 4;      // 0..4092
    int c = blockIdx.y, b = blockIdx.z;
    const float* mb = m + ((size_t)b*NCH + c)*LFP;
    const float* kb = g_ker + (size_t)b*3*LFP;
    float4 m0  = *(const float4*)&mb[t];
    float mprev = (t > 0) ? mb[t-1] : 0.f;
    float mnext = mb[t+4];
    float4 kk0 = *(const float4*)&kb[t];
    float4 kk1 = *(const float4*)&kb[LFP + t];
    float4 kk2 = *(const float4*)&kb[2*LFP + t];
    float al = aP[c];
    float o0 = kk1.x*m0.x + kk0.x*mprev + kk2.x*m0.y;
    float o1 = kk1.y*m0.y + kk0.y*m0.x  + kk2.y*m0.z;
    float o2 = kk1.z*m0.z + kk0.z*m0.y  + kk2.z*m0.w;
    float o3 = kk1.w*m0.w + kk0.w*m0.z  + kk2.w*mnext;
    o0 = (o0 >= 0.f) ? o0 : al*o0;
    o1 = (o1 >= 0.f) ? o1 : al*o1;
    o2 = (o2 >= 0.f) ? o2 : al*o2;
    o3 = (o3 >= 0.f) ? o3 : al*o3;
    if (t + 3 >= LF) o3 = 0.f;
    *(float4*)&outp[((size_t)b*NCH + c)*LFP + t] = make_float4(o0, o1, o2, o3);
}

// ---------------- decoder: per-frame 16-tap projection ----------------
__global__ __launch_bounds__(256) void k_dpart(const float* __restrict__ masked,
                                               const float* __restrict__ dw)
{
    __shared__ float sw[NCH*16];
    for (int i = threadIdx.x; i < NCH*16; i += 256) sw[i] = dw[i];
    __syncthreads();
    int b = blockIdx.y;
    int t = blockIdx.x*256 + threadIdx.x;   // 0..4095
    float acc[16];
    #pragma unroll
    for (int l = 0; l < 16; l++) acc[l] = 0.f;
    const float* mb = masked + (size_t)b*NCH*LFP + t;
    #pragma unroll 4
    for (int c = 0; c < NCH; c++) {
        float v = mb[(size_t)c*LFP];
        #pragma unroll
        for (int l = 0; l < 16; l++) acc[l] += v * sw[c*16 + l];
    }
    bool pad = (t >= LF);
    #pragma unroll
    for (int l = 0; l < 16; l++)
        g_part[((size_t)b*16 + l)*LFP + t] = pad ? 0.f : acc[l];
}

__global__ void k_combine(float* __restrict__ outp)
{
    int b = blockIdx.y;
    int s = blockIdx.x*256 + threadIdx.x;
    int t0 = s >> 3, l = s & 7;
    float v = g_part[((size_t)b*16 + l)*LFP + t0];        // pad rows are 0
    if (t0 >= 1) v += g_part[((size_t)b*16 + l + 8)*LFP + t0 - 1];
    outp[(size_t)b*SEQLEN + s] = v;
}

// ---------------- driver ----------------
extern "C" void kernel_launch(void* const* d_in, const int* in_sizes, int n_in,
                              void* d_out, int out_size)
{
    (void)in_sizes; (void)n_in; (void)out_size;
    const float* noisy_ac    = (const float*)d_in[0];
    const float* noisy_bc    = (const float*)d_in[1];
    const float* ac_w        = (const float*)d_in[2];
    const float* bc_w        = (const float*)d_in[3];
    const float* me_ln_g     = (const float*)d_in[4];
    const float* me_ln_b     = (const float*)d_in[5];
    const float* me_init_w   = (const float*)d_in[6];
    const float* me_init_b   = (const float*)d_in[7];
    const float* blk_ln_g    = (const float*)d_in[8];
    const float* blk_ln_b    = (const float*)d_in[9];
    const float* blk_act_a   = (const float*)d_in[10];
    const float* inv_w1      = (const float*)d_in[11];
    const float* inv_b1      = (const float*)d_in[12];
    const float* inv_w2      = (const float*)d_in[13];
    const float* inv_b2      = (const float*)d_in[14];
    const float* inv_prelu_a = (const float*)d_in[15];
    const float* skip_w      = (const float*)d_in[16];
    const float* skip_b      = (const float*)d_in[17];
    const float* me_final_w  = (const float*)d_in[18];
    const float* me_final_b  = (const float*)d_in[19];
    const float* dec_w       = (const float*)d_in[20];
    float* out = (float*)d_out;

    float *p_enc, *p_x, *p_xn, *p_m1, *p_m2;
    cudaGetSymbolAddress((void**)&p_enc, g_enc);
    cudaGetSymbolAddress((void**)&p_x,   g_x);
    cudaGetSymbolAddress((void**)&p_xn,  g_xn);
    cudaGetSymbolAddress((void**)&p_m1,  g_m1);
    cudaGetSymbolAddress((void**)&p_m2,  g_m2);

    dim3 lnGrid(128, NB), lnBlk(32, 8);
    dim3 pwGrid(32, 4, NB);                 // 128-t tiles, 64-o tiles, batch
    dim3 invGrid(4, NCH, NB);

    k_prep<<<dim3(12, 3), 256>>>(inv_w1, inv_b1, inv_w2, inv_b2);
    k_enc <<<dim3(128, NB), dim3(32, 8)>>>(noisy_ac, noisy_bc, ac_w, bc_w, p_enc);
    k_ln  <<<lnGrid, lnBlk>>>(p_enc, p_xn, me_ln_g, me_ln_b, nullptr);
    k_pw  <<<pwGrid, 256>>>(me_init_w, me_init_b, p_xn, nullptr, nullptr, p_x, 0);

    for (int blk = 0; blk < 4; blk++) {
        k_ln<<<lnGrid, lnBlk>>>(p_x, p_xn,
                                blk_ln_g + blk*NCH, blk_ln_b + blk*NCH,
                                blk_act_a + blk);
        k_ker<<<dim3(32, NB), 128>>>(blk*3 + 0, p_xn);
        k_inv<<<invGrid, 256>>>(p_xn, inv_prelu_a + (blk*3 + 0)*NCH, p_m1);
        k_ker<<<dim3(32, NB), 128>>>(blk*3 + 1, p_m1);
        k_inv<<<invGrid, 256>>>(p_m1, inv_prelu_a + (blk*3 + 1)*NCH, p_m2);
        k_ker<<<dim3(32, NB), 128>>>(blk*3 + 2, p_m2);
        k_inv<<<invGrid, 256>>>(p_m2, inv_prelu_a + (blk*3 + 2)*NCH, p_m1);
        k_pw<<<pwGrid, 256>>>(skip_w + (size_t)blk*NCH*NCH, skip_b + blk*NCH,
                              p_xn, p_m1, nullptr, p_x, 1);
    }

    k_pw<<<pwGrid, 256>>>(me_final_w, me_final_b, p_x, nullptr, p_enc, p_xn, 2);
    k_dpart  <<<dim3(16, NB), 256>>>(p_xn, dec_w);
    k_combine<<<dim3(128, NB), 256>>>(out);
}

// round 3
// speedup vs baseline: 1.6190x; 1.0849x over previous
#include <cuda_runtime.h>
#include <cuda_bf16.h>
#include <stdint.h>

#define LF     4095
#define LFP    4096
#define NCH    256
#define NB     4
#define SEQLEN 32768
#define EPSF   1e-5f

// ---------------- scratch (static device globals; no allocation) ----------------
__device__ float g_enc [NB*NCH*LFP];
__device__ float g_x   [NB*NCH*LFP];
__device__ float g_m1  [NB*NCH*LFP];
__device__ float g_msk [NB*NCH*LFP];
__device__ __nv_bfloat16 g_xnh[NB*NCH*LFP];
__device__ __nv_bfloat16 g_xnl[NB*NCH*LFP];
__device__ __nv_bfloat16 g_x3h[NB*NCH*LFP];
__device__ __nv_bfloat16 g_x3l[NB*NCH*LFP];
__device__ float g_part[NB*16*LFP];
__device__ float g_wc  [12*3*NCH];
__device__ float g_bcol[12*3];

__device__ __forceinline__ void split1(float x, __nv_bfloat16& h, __nv_bfloat16& l)
{
    h = __float2bfloat16(x);
    l = __float2bfloat16(x - __bfloat162float(h));
}

// ---------------- collapse w2@w1 (+ bias) per (block,p,j) ----------------
__global__ void k_prep(const float* __restrict__ w1, const float* __restrict__ b1,
                       const float* __restrict__ w2, const float* __restrict__ b2)
{
    int bp = blockIdx.x;
    int j  = blockIdx.y;
    int c  = threadIdx.x;
    const float* w1p = w1 + (size_t)bp*64*NCH;
    const float* w2p = w2 + ((size_t)bp*3 + j)*64;
    float acc = 0.f;
    #pragma unroll 8
    for (int cr = 0; cr < 64; cr++) acc += w2p[cr] * w1p[(size_t)cr*NCH + c];
    g_wc[((size_t)bp*3 + j)*NCH + c] = acc;
    if (c == 0) {
        const float* b1p = b1 + bp*64;
        float bb = b2[bp*3 + j];
        for (int cr = 0; cr < 64; cr++) bb += w2p[cr]*b1p[cr];
        g_bcol[bp*3 + j] = bb;
    }
}

// ---------------- encoder + fused channel-LN ----------------
__global__ void k_enc_ln(const float* __restrict__ ac, const float* __restrict__ bc,
                         const float* __restrict__ acw, const float* __restrict__ bcw,
                         const float* __restrict__ lng, const float* __restrict__ lnb,
                         float* __restrict__ enc,
                         __nv_bfloat16* __restrict__ xnh, __nv_bfloat16* __restrict__ xnl)
{
    int b  = blockIdx.y;
    int t0 = blockIdx.x * 32;
    int tx = threadIdx.x, ty = threadIdx.y;
    __shared__ float sa[264], sb[264];
    __shared__ float ss[8][33], sq[8][33];
    int tid  = ty*32 + tx;
    int base = t0 * 8;
    for (int i = tid; i < 264; i += 256) {
        int gi = base + i;
        sa[i] = (gi < SEQLEN) ? ac[(size_t)b*SEQLEN + gi] : 0.f;
        sb[i] = (gi < SEQLEN) ? bc[(size_t)b*SEQLEN + gi] : 0.f;
    }
    __syncthreads();
    int t = t0 + tx;
    bool valid = (t < LF);
    const size_t bbase = (size_t)b*NCH*LFP;
    float vals[32];
    float s = 0.f, q = 0.f;
    #pragma unroll
    for (int i = 0; i < 32; i++) {
        int n = ty + i*8;
        float acc = 0.f;
        #pragma unroll
        for (int l = 0; l < 16; l++)
            acc += sa[tx*8 + l]*acw[n*16 + l] + sb[tx*8 + l]*bcw[n*16 + l];
        if (!valid) acc = 0.f;
        vals[i] = acc; s += acc; q += acc*acc;
        enc[bbase + (size_t)n*LFP + t] = acc;
    }
    ss[ty][tx] = s; sq[ty][tx] = q;
    __syncthreads();
    if (ty == 0) {
        float S = 0.f, Q = 0.f;
        #pragma unroll
        for (int j = 0; j < 8; j++) { S += ss[j][tx]; Q += sq[j][tx]; }
        float mu  = S * (1.f/NCH);
        float var = Q * (1.f/NCH) - mu*mu;
        ss[0][tx] = mu;
        sq[0][tx] = rsqrtf(var + EPSF);
    }
    __syncthreads();
    float mu = ss[0][tx], rs = sq[0][tx];
    #pragma unroll
    for (int i = 0; i < 32; i++) {
        int c = ty + i*8;
        float v = valid ? (vals[i] - mu)*rs*lng[c] + lnb[c] : 0.f;
        __nv_bfloat16 h, l; split1(v, h, l);
        size_t gi = bbase + (size_t)c*LFP + t;
        xnh[gi] = h; xnl[gi] = l;
    }
}

// ---------------- tensor-core pointwise GEMM (bf16x3 split, B pre-split in gmem) ---
// mode 0: fp32 out; 1: +addsrc fp32 out; 2: relu(.)*enc fp32 out; 3: +addsrc split out
#define LDSM4(R, addr)  asm volatile("ldmatrix.sync.aligned.m8n8.x4.shared.b16 {%0,%1,%2,%3}, [%4];" \
    : "=r"(R[0]),"=r"(R[1]),"=r"(R[2]),"=r"(R[3]) : "r"(addr))
#define LDSM4T(R, addr) asm volatile("ldmatrix.sync.aligned.m8n8.x4.trans.shared.b16 {%0,%1,%2,%3}, [%4];" \
    : "=r"(R[0]),"=r"(R[1]),"=r"(R[2]),"=r"(R[3]) : "r"(addr))
#define MMA_BF16(D, A, B0, B1) asm volatile( \
    "mma.sync.aligned.m16n8k16.row.col.f32.bf16.bf16.f32 " \
    "{%0,%1,%2,%3}, {%4,%5,%6,%7}, {%8,%9}, {%0,%1,%2,%3};" \
    : "+f"(D[0]), "+f"(D[1]), "+f"(D[2]), "+f"(D[3]) \
    : "r"(A[0]), "r"(A[1]), "r"(A[2]), "r"(A[3]), "r"(B0), "r"(B1))

__device__ __forceinline__ void splitStore8(const float* v, __nv_bfloat16* hp, __nv_bfloat16* lp)
{
    unsigned hh[4], ll[4];
    #pragma unroll
    for (int i = 0; i < 4; i++) {
        float x0 = v[2*i], x1 = v[2*i+1];
        __nv_bfloat16 h0 = __float2bfloat16(x0), h1 = __float2bfloat16(x1);
        __nv_bfloat16 l0 = __float2bfloat16(x0 - __bfloat162float(h0));
        __nv_bfloat16 l1 = __float2bfloat16(x1 - __bfloat162float(h1));
        hh[i] = ((unsigned)__bfloat16_as_ushort(h1) << 16) | __bfloat16_as_ushort(h0);
        ll[i] = ((unsigned)__bfloat16_as_ushort(l1) << 16) | __bfloat16_as_ushort(l0);
    }
    *(uint4*)hp = make_uint4(hh[0],hh[1],hh[2],hh[3]);
    *(uint4*)lp = make_uint4(ll[0],ll[1],ll[2],ll[3]);
}

__global__ __launch_bounds__(256, 2) void k_pw(
        const float* __restrict__ W, const float* __restrict__ bias,
        const __nv_bfloat16* __restrict__ Xh, const __nv_bfloat16* __restrict__ Xl,
        const float* __restrict__ addsrc, const float* __restrict__ encp,
        float* __restrict__ outf,
        __nv_bfloat16* __restrict__ outh, __nv_bfloat16* __restrict__ outl,
        int mode)
{
    const int b  = blockIdx.z;
    const int t0 = blockIdx.x * 128;
    const int o0 = blockIdx.y * 64;
    const size_t bbase = (size_t)b*NCH*LFP;

    __shared__ __align__(16) __nv_bfloat16 Ah[64][40];
    __shared__ __align__(16) __nv_bfloat16 Al[64][40];
    __shared__ __align__(16) __nv_bfloat16 Bh[32][136];
    __shared__ __align__(16) __nv_bfloat16 Bl[32][136];

    const int tid  = threadIdx.x;
    const int lane = tid & 31, warp = tid >> 5;
    const int wm = warp & 1, wn = warp >> 1;

    const int ar = tid >> 2, ac = (tid & 3) << 3;  // A stage
    const int br = tid >> 3, bc = (tid & 7) << 3;  // B stage: row 0..31, col {0..56}

    float aR[8];
    uint4 bh0, bh1, bl0, bl1;
    {
        const float* wp = &W[(size_t)(o0 + ar)*NCH + ac];
        *(float4*)&aR[0] = *(const float4*)&wp[0];
        *(float4*)&aR[4] = *(const float4*)&wp[4];
        size_t xoff = bbase + (size_t)br*LFP + t0 + bc;
        bh0 = *(const uint4*)&Xh[xoff];
        bh1 = *(const uint4*)&Xh[xoff + 64];
        bl0 = *(const uint4*)&Xl[xoff];
        bl1 = *(const uint4*)&Xl[xoff + 64];
    }

    float acc[2][4][4];
    #pragma unroll
    for (int i = 0; i < 2; i++)
        #pragma unroll
        for (int j = 0; j < 4; j++)
            #pragma unroll
            for (int r = 0; r < 4; r++) acc[i][j][r] = 0.f;

    #pragma unroll 1
    for (int kt = 0; kt < 8; kt++) {
        splitStore8(aR, &Ah[ar][ac], &Al[ar][ac]);
        *(uint4*)&Bh[br][bc]      = bh0;
        *(uint4*)&Bh[br][bc + 64] = bh1;
        *(uint4*)&Bl[br][bc]      = bl0;
        *(uint4*)&Bl[br][bc + 64] = bl1;
        __syncthreads();
        if (kt < 7) {
            int k0 = (kt + 1) * 32;
            const float* wp = &W[(size_t)(o0 + ar)*NCH + k0 + ac];
            *(float4*)&aR[0] = *(const float4*)&wp[0];
            *(float4*)&aR[4] = *(const float4*)&wp[4];
            size_t xoff = bbase + (size_t)(k0 + br)*LFP + t0 + bc;
            bh0 = *(const uint4*)&Xh[xoff];
            bh1 = *(const uint4*)&Xh[xoff + 64];
            bl0 = *(const uint4*)&Xl[xoff];
            bl1 = *(const uint4*)&Xl[xoff + 64];
        }
        #pragma unroll
        for (int ks = 0; ks < 2; ks++) {
            const int kb = ks * 16;
            unsigned a_hi[2][4], a_lo[2][4], b_hi[2][4], b_lo[2][4];
            #pragma unroll
            for (int mt = 0; mt < 2; mt++) {
                int rowA = wm*32 + mt*16 + (lane & 15);
                int colA = kb + ((lane >> 4) << 3);
                unsigned sa = (unsigned)__cvta_generic_to_shared(&Ah[rowA][colA]);
                LDSM4(a_hi[mt], sa);
                unsigned sl = (unsigned)__cvta_generic_to_shared(&Al[rowA][colA]);
                LDSM4(a_lo[mt], sl);
            }
            #pragma unroll
            for (int ng = 0; ng < 2; ng++) {
                int rowB = kb + (lane & 15);
                int colB = wn*32 + ng*16 + ((lane >> 4) << 3);
                unsigned sb = (unsigned)__cvta_generic_to_shared(&Bh[rowB][colB]);
                LDSM4T(b_hi[ng], sb);
                unsigned sl = (unsigned)__cvta_generic_to_shared(&Bl[rowB][colB]);
                LDSM4T(b_lo[ng], sl);
            }
            #pragma unroll
            for (int mt = 0; mt < 2; mt++)
                #pragma unroll
                for (int ng = 0; ng < 2; ng++)
                    #pragma unroll
                    for (int hf = 0; hf < 2; hf++) {
                        int nt = ng*2 + hf;
                        MMA_BF16(acc[mt][nt], a_hi[mt], b_hi[ng][hf*2], b_hi[ng][hf*2+1]);
                        MMA_BF16(acc[mt][nt], a_hi[mt], b_lo[ng][hf*2], b_lo[ng][hf*2+1]);
                        MMA_BF16(acc[mt][nt], a_lo[mt], b_hi[ng][hf*2], b_hi[ng][hf*2+1]);
                    }
        }
        __syncthreads();
    }

    const int g8 = lane >> 2, tq = lane & 3;
    #pragma unroll
    for (int mt = 0; mt < 2; mt++)
        #pragma unroll
        for (int rr = 0; rr < 2; rr++) {
            int o = o0 + wm*32 + mt*16 + rr*8 + g8;
            float bv = bias[o];
            size_t rowo = bbase + (size_t)o*LFP;
            #pragma unroll
            for (int nt = 0; nt < 4; nt++) {
                int t = t0 + wn*32 + nt*8 + tq*2;
                float v0 = acc[mt][nt][rr*2+0] + bv;
                float v1 = acc[mt][nt][rr*2+1] + bv;
                if (mode == 1 || mode == 3) {
                    float2 ad = *(const float2*)&addsrc[rowo + t];
                    v0 += ad.x; v1 += ad.y;
                } else if (mode == 2) {
                    float2 e = *(const float2*)&encp[rowo + t];
                    v0 = fmaxf(v0, 0.f) * e.x;
                    v1 = fmaxf(v1, 0.f) * e.y;
                }
                if (t     >= LF) v0 = 0.f;
                if (t + 1 >= LF) v1 = 0.f;
                if (mode == 3) {
                    __nv_bfloat16 h0, l0, h1, l1;
                    split1(v0, h0, l0); split1(v1, h1, l1);
                    *(__nv_bfloat162*)&outh[rowo + t] = __nv_bfloat162(h0, h1);
                    *(__nv_bfloat162*)&outl[rowo + t] = __nv_bfloat162(l0, l1);
                } else {
                    *(float2*)&outf[rowo + t] = make_float2(v0, v1);
                }
            }
        }
}

// ---------------- fused block chain: prelu -> LN -> 3x(involution + prelu) --------
// CTA: all 256 channels x 38-frame tile (interior 32, halo 3).
__global__ __launch_bounds__(256) void k_invchain(
    const float* __restrict__ x,
    const float* __restrict__ lng, const float* __restrict__ lnb,
    const float* __restrict__ alphaScalar,
    const float* __restrict__ prelu_a,      // [3*NCH] for this block
    int bp0,
    __nv_bfloat16* __restrict__ xnh, __nv_bfloat16* __restrict__ xnl,
    float* __restrict__ mout)
{
    extern __shared__ float dyn[];
    float* bufA = dyn;                  // [256][41]
    float* bufB = dyn + 256*41;
    __shared__ float w_s[3*NCH];
    __shared__ float g_sln[NCH], b_sln[NCH], al_s[NCH];
    __shared__ float ker_s[3][41];
    __shared__ float mu_s[41], rs_s[41];
    __shared__ float psum[128];

    const int b    = blockIdx.y;
    const int t0   = blockIdx.x * 32;
    const int tid  = threadIdx.x;
    const int lane = tid & 31, warp = tid >> 5;
    const float aS = *alphaScalar;
    const size_t bbase = (size_t)b*NCH*LFP;

    if (tid < NCH) { g_sln[tid] = lng[tid]; b_sln[tid] = lnb[tid]; }

    // P0: load tile with scalar prelu; zero outside [0, LF)
    for (int c = warp; c < NCH; c += 8) {
        const float* row = x + bbase + (size_t)c*LFP;
        #pragma unroll
        for (int base = 0; base < 64; base += 32) {
            int tt = base + lane;
            if (tt < 38) {
                int tg = t0 - 3 + tt;
                float v = (tg >= 0 && tg < LF) ? row[tg] : 0.f;
                v = (v >= 0.f) ? v : aS*v;
                bufA[c*41 + tt] = v;
            }
        }
    }
    __syncthreads();

    // P1: LN stats per frame (warp per column)
    for (int tt = warp; tt < 38; tt += 8) {
        float s = 0.f, q = 0.f;
        #pragma unroll
        for (int c = lane; c < NCH; c += 32) {
            float v = bufA[c*41 + tt];
            s += v; q += v*v;
        }
        #pragma unroll
        for (int off = 16; off > 0; off >>= 1) {
            s += __shfl_xor_sync(0xffffffffu, s, off);
            q += __shfl_xor_sync(0xffffffffu, q, off);
        }
        if (lane == 0) {
            float mu  = s * (1.f/NCH);
            float var = q * (1.f/NCH) - mu*mu;
            mu_s[tt] = mu;
            rs_s[tt] = rsqrtf(var + EPSF);
        }
    }
    __syncthreads();

    // P2: normalize in place; write split-bf16 xn for interior frames
    for (int c = warp; c < NCH; c += 8) {
        float gg = g_sln[c], bb = b_sln[c];
        #pragma unroll
        for (int base = 0; base < 64; base += 32) {
            int tt = base + lane;
            if (tt < 38) {
                int tg = t0 - 3 + tt;
                float v = (bufA[c*41 + tt] - mu_s[tt]) * rs_s[tt] * gg + bb;
                if (tg < 0 || tg >= LF) v = 0.f;
                bufA[c*41 + tt] = v;
                if (tt >= 3 && tt < 35) {
                    __nv_bfloat16 h, l; split1(v, h, l);
                    size_t gi = bbase + (size_t)c*LFP + (size_t)(t0 + tt - 3);
                    xnh[gi] = h; xnl[gi] = l;
                }
            }
        }
    }
    __syncthreads();

    // P3: three involution steps (ping-pong bufA/bufB)
    float* src = bufA; float* dst = bufB;
    #pragma unroll 1
    for (int s = 0; s < 3; s++) {
        const float* wsrc = g_wc + (size_t)(bp0 + s)*3*NCH;
        for (int i = tid; i < 3*NCH; i += 256) w_s[i] = wsrc[i];
        if (tid < NCH) al_s[tid] = prelu_a[s*NCH + tid];
        __syncthreads();

        // kernel-gen: 114 items (j in 0..2, tt in 0..37), split over two c-halves
        int item = (tid < 114) ? tid : ((tid >= 128 && tid < 242) ? tid - 128 : -1);
        float accp = 0.f;
        int jj = 0, ttk = 0;
        if (item >= 0) {
            jj = item / 38; ttk = item - jj*38;
            int c0 = (tid < 128) ? 0 : 128;
            const float* wrow = w_s + jj*NCH;
            #pragma unroll 4
            for (int c = c0; c < c0 + 128; c++)
                accp += wrow[c] * src[c*41 + ttk];
        }
        if (tid >= 128 && item >= 0) psum[item] = accp;
        __syncthreads();
        if (tid < 114)
            ker_s[jj][ttk] = accp + psum[item] + g_bcol[(bp0+s)*3 + jj];
        __syncthreads();

        // apply + per-channel prelu; valid output range shrinks by 1 per step
        int lo = 1 + s, hi = 37 - s;
        for (int c = warp; c < NCH; c += 8) {
            float al = al_s[c];
            const float* srow = src + c*41;
            float* drow = dst + c*41;
            for (int base = lo; base < hi; base += 32) {
                int tt = base + lane;
                if (tt < hi) {
                    float v = ker_s[1][tt]*srow[tt] + ker_s[0][tt]*srow[tt-1]
                            + ker_s[2][tt]*srow[tt+1];
                    v = (v >= 0.f) ? v : al*v;
                    int tg = t0 - 3 + tt;
                    if (tg < 0 || tg >= LF) v = 0.f;
                    drow[tt] = v;
                }
            }
        }
        __syncthreads();
        float* tmp = src; src = dst; dst = tmp;
    }

    // P4: write final interior (result in src)
    for (int c = warp; c < NCH; c += 8)
        mout[bbase + (size_t)c*LFP + t0 + lane] = src[c*41 + 3 + lane];
}

// ---------------- decoder ----------------
__global__ __launch_bounds__(256) void k_dpart(const float* __restrict__ masked,
                                               const float* __restrict__ dw)
{
    __shared__ float sw[NCH*16];
    for (int i = threadIdx.x; i < NCH*16; i += 256) sw[i] = dw[i];
    __syncthreads();
    int b = blockIdx.y;
    int t = blockIdx.x*256 + threadIdx.x;
    float acc[16];
    #pragma unroll
    for (int l = 0; l < 16; l++) acc[l] = 0.f;
    const float* mb = masked + (size_t)b*NCH*LFP + t;
    #pragma unroll 8
    for (int c = 0; c < NCH; c++) {
        float v = mb[(size_t)c*LFP];
        #pragma unroll
        for (int l = 0; l < 16; l++) acc[l] += v * sw[c*16 + l];
    }
    bool pad = (t >= LF);
    #pragma unroll
    for (int l = 0; l < 16; l++)
        g_part[((size_t)b*16 + l)*LFP + t] = pad ? 0.f : acc[l];
}

__global__ void k_combine(float* __restrict__ outp)
{
    int b = blockIdx.y;
    int s = blockIdx.x*256 + threadIdx.x;
    int t0 = s >> 3, l = s & 7;
    float v = g_part[((size_t)b*16 + l)*LFP + t0];
    if (t0 >= 1) v += g_part[((size_t)b*16 + l + 8)*LFP + t0 - 1];
    outp[(size_t)b*SEQLEN + s] = v;
}

// ---------------- driver ----------------
extern "C" void kernel_launch(void* const* d_in, const int* in_sizes, int n_in,
                              void* d_out, int out_size)
{
    (void)in_sizes; (void)n_in; (void)out_size;
    const float* noisy_ac    = (const float*)d_in[0];
    const float* noisy_bc    = (const float*)d_in[1];
    const float* ac_w        = (const float*)d_in[2];
    const float* bc_w        = (const float*)d_in[3];
    const float* me_ln_g     = (const float*)d_in[4];
    const float* me_ln_b     = (const float*)d_in[5];
    const float* me_init_w   = (const float*)d_in[6];
    const float* me_init_b   = (const float*)d_in[7];
    const float* blk_ln_g    = (const float*)d_in[8];
    const float* blk_ln_b    = (const float*)d_in[9];
    const float* blk_act_a   = (const float*)d_in[10];
    const float* inv_w1      = (const float*)d_in[11];
    const float* inv_b1      = (const float*)d_in[12];
    const float* inv_w2      = (const float*)d_in[13];
    const float* inv_b2      = (const float*)d_in[14];
    const float* inv_prelu_a = (const float*)d_in[15];
    const float* skip_w      = (const float*)d_in[16];
    const float* skip_b      = (const float*)d_in[17];
    const float* me_final_w  = (const float*)d_in[18];
    const float* me_final_b  = (const float*)d_in[19];
    const float* dec_w       = (const float*)d_in[20];
    float* out = (float*)d_out;

    float *p_enc, *p_x, *p_m1, *p_msk;
    __nv_bfloat16 *p_xnh, *p_xnl, *p_x3h, *p_x3l;
    cudaGetSymbolAddress((void**)&p_enc, g_enc);
    cudaGetSymbolAddress((void**)&p_x,   g_x);
    cudaGetSymbolAddress((void**)&p_m1,  g_m1);
    cudaGetSymbolAddress((void**)&p_msk, g_msk);
    cudaGetSymbolAddress((void**)&p_xnh, g_xnh);
    cudaGetSymbolAddress((void**)&p_xnl, g_xnl);
    cudaGetSymbolAddress((void**)&p_x3h, g_x3h);
    cudaGetSymbolAddress((void**)&p_x3l, g_x3l);

    const int invSmem = 2*256*41*sizeof(float);   // 83968 B
    cudaFuncSetAttribute(k_invchain, cudaFuncAttributeMaxDynamicSharedMemorySize, invSmem);

    dim3 pwGrid(32, 4, NB);

    k_prep  <<<dim3(12, 3), 256>>>(inv_w1, inv_b1, inv_w2, inv_b2);
    k_enc_ln<<<dim3(128, NB), dim3(32, 8)>>>(noisy_ac, noisy_bc, ac_w, bc_w,
                                             me_ln_g, me_ln_b, p_enc, p_xnh, p_xnl);
    k_pw<<<pwGrid, 256>>>(me_init_w, me_init_b, p_xnh, p_xnl,
                          nullptr, nullptr, p_x, nullptr, nullptr, 0);

    for (int blk = 0; blk < 4; blk++) {
        k_invchain<<<dim3(128, NB), 256, invSmem>>>(
            p_x, blk_ln_g + blk*NCH, blk_ln_b + blk*NCH,
            blk_act_a + blk, inv_prelu_a + (size_t)blk*3*NCH, blk*3,
            p_xnh, p_xnl, p_m1);
        if (blk < 3)
            k_pw<<<pwGrid, 256>>>(skip_w + (size_t)blk*NCH*NCH, skip_b + blk*NCH,
                                  p_xnh, p_xnl, p_m1, nullptr,
                                  p_x, nullptr, nullptr, 1);
        else
            k_pw<<<pwGrid, 256>>>(skip_w + (size_t)blk*NCH*NCH, skip_b + blk*NCH,
                                  p_xnh, p_xnl, p_m1, nullptr,
                                  nullptr, p_x3h, p_x3l, 3);
    }

    k_pw<<<pwGrid, 256>>>(me_final_w, me_final_b, p_x3h, p_x3l,
                          nullptr, p_enc, p_msk, nullptr, nullptr, 2);
    k_dpart  <<<dim3(16, NB), 256>>>(p_msk, dec_w);
    k_combine<<<dim3(128, NB), 256>>>(out);
}

// round 4
// speedup vs baseline: 3.1709x; 1.9586x over previous
#include <cuda_runtime.h>
#include <cuda_bf16.h>
#include <stdint.h>

#define LF     4095
#define LFP    4096
#define NCH    256
#define NB     4
#define SEQLEN 32768
#define EPSF   1e-5f
#define TILE_INT 26

// ---------------- scratch (static device globals; no allocation) ----------------
__device__ float g_enc [NB*NCH*LFP];
__device__ float g_x   [NB*NCH*LFP];
__device__ float g_m1  [NB*NCH*LFP];
__device__ float g_msk [NB*NCH*LFP];
__device__ __nv_bfloat16 g_xnh[NB*NCH*LFP];
__device__ __nv_bfloat16 g_xnl[NB*NCH*LFP];
__device__ __nv_bfloat16 g_x3h[NB*NCH*LFP];
__device__ __nv_bfloat16 g_x3l[NB*NCH*LFP];
__device__ float g_part[NB*16*LFP];
__device__ float g_wc  [12*3*NCH];
__device__ float g_bcol[12*3];

__device__ __forceinline__ void split1(float x, __nv_bfloat16& h, __nv_bfloat16& l)
{
    h = __float2bfloat16(x);
    l = __float2bfloat16(x - __bfloat162float(h));
}

// ---------------- collapse w2@w1 (+ bias) per (block,p,j) ----------------
__global__ void k_prep(const float* __restrict__ w1, const float* __restrict__ b1,
                       const float* __restrict__ w2, const float* __restrict__ b2)
{
    int bp = blockIdx.x;
    int j  = blockIdx.y;
    int c  = threadIdx.x;
    const float* w1p = w1 + (size_t)bp*64*NCH;
    const float* w2p = w2 + ((size_t)bp*3 + j)*64;
    float acc = 0.f;
    #pragma unroll 8
    for (int cr = 0; cr < 64; cr++) acc += w2p[cr] * w1p[(size_t)cr*NCH + c];
    g_wc[((size_t)bp*3 + j)*NCH + c] = acc;
    if (c == 0) {
        const float* b1p = b1 + bp*64;
        float bb = b2[bp*3 + j];
        for (int cr = 0; cr < 64; cr++) bb += w2p[cr]*b1p[cr];
        g_bcol[bp*3 + j] = bb;
    }
}

// ---------------- encoder + fused channel-LN ----------------
__global__ void k_enc_ln(const float* __restrict__ ac, const float* __restrict__ bc,
                         const float* __restrict__ acw, const float* __restrict__ bcw,
                         const float* __restrict__ lng, const float* __restrict__ lnb,
                         float* __restrict__ enc,
                         __nv_bfloat16* __restrict__ xnh, __nv_bfloat16* __restrict__ xnl)
{
    int b  = blockIdx.y;
    int t0 = blockIdx.x * 32;
    int tx = threadIdx.x, ty = threadIdx.y;
    __shared__ float sa[264], sb[264];
    __shared__ float ss[8][33], sq[8][33];
    int tid  = ty*32 + tx;
    int base = t0 * 8;
    for (int i = tid; i < 264; i += 256) {
        int gi = base + i;
        sa[i] = (gi < SEQLEN) ? ac[(size_t)b*SEQLEN + gi] : 0.f;
        sb[i] = (gi < SEQLEN) ? bc[(size_t)b*SEQLEN + gi] : 0.f;
    }
    __syncthreads();
    int t = t0 + tx;
    bool valid = (t < LF);
    const size_t bbase = (size_t)b*NCH*LFP;
    float vals[32];
    float s = 0.f, q = 0.f;
    #pragma unroll
    for (int i = 0; i < 32; i++) {
        int n = ty + i*8;
        float acc = 0.f;
        #pragma unroll
        for (int l = 0; l < 16; l++)
            acc += sa[tx*8 + l]*acw[n*16 + l] + sb[tx*8 + l]*bcw[n*16 + l];
        if (!valid) acc = 0.f;
        vals[i] = acc; s += acc; q += acc*acc;
        enc[bbase + (size_t)n*LFP + t] = acc;
    }
    ss[ty][tx] = s; sq[ty][tx] = q;
    __syncthreads();
    if (ty == 0) {
        float S = 0.f, Q = 0.f;
        #pragma unroll
        for (int j = 0; j < 8; j++) { S += ss[j][tx]; Q += sq[j][tx]; }
        float mu  = S * (1.f/NCH);
        float var = Q * (1.f/NCH) - mu*mu;
        ss[0][tx] = mu;
        sq[0][tx] = rsqrtf(var + EPSF);
    }
    __syncthreads();
    float mu = ss[0][tx], rs = sq[0][tx];
    #pragma unroll
    for (int i = 0; i < 32; i++) {
        int c = ty + i*8;
        float v = valid ? (vals[i] - mu)*rs*lng[c] + lnb[c] : 0.f;
        __nv_bfloat16 h, l; split1(v, h, l);
        size_t gi = bbase + (size_t)c*LFP + t;
        xnh[gi] = h; xnl[gi] = l;
    }
}

// ---------------- tensor-core pointwise GEMM ----------------
#define LDSM4(R, addr)  asm volatile("ldmatrix.sync.aligned.m8n8.x4.shared.b16 {%0,%1,%2,%3}, [%4];" \
    : "=r"(R[0]),"=r"(R[1]),"=r"(R[2]),"=r"(R[3]) : "r"(addr))
#define LDSM4T(R, addr) asm volatile("ldmatrix.sync.aligned.m8n8.x4.trans.shared.b16 {%0,%1,%2,%3}, [%4];" \
    : "=r"(R[0]),"=r"(R[1]),"=r"(R[2]),"=r"(R[3]) : "r"(addr))
#define MMA_BF16(D, A, B0, B1) asm volatile( \
    "mma.sync.aligned.m16n8k16.row.col.f32.bf16.bf16.f32 " \
    "{%0,%1,%2,%3}, {%4,%5,%6,%7}, {%8,%9}, {%0,%1,%2,%3};" \
    : "+f"(D[0]), "+f"(D[1]), "+f"(D[2]), "+f"(D[3]) \
    : "r"(A[0]), "r"(A[1]), "r"(A[2]), "r"(A[3]), "r"(B0), "r"(B1))

__device__ __forceinline__ void splitStore8(const float* v, __nv_bfloat16* hp, __nv_bfloat16* lp)
{
    unsigned hh[4], ll[4];
    #pragma unroll
    for (int i = 0; i < 4; i++) {
        float x0 = v[2*i], x1 = v[2*i+1];
        __nv_bfloat16 h0 = __float2bfloat16(x0), h1 = __float2bfloat16(x1);
        __nv_bfloat16 l0 = __float2bfloat16(x0 - __bfloat162float(h0));
        __nv_bfloat16 l1 = __float2bfloat16(x1 - __bfloat162float(h1));
        hh[i] = ((unsigned)__bfloat16_as_ushort(h1) << 16) | __bfloat16_as_ushort(h0);
        ll[i] = ((unsigned)__bfloat16_as_ushort(l1) << 16) | __bfloat16_as_ushort(l0);
    }
    *(uint4*)hp = make_uint4(hh[0],hh[1],hh[2],hh[3]);
    *(uint4*)lp = make_uint4(ll[0],ll[1],ll[2],ll[3]);
}

__global__ __launch_bounds__(256, 2) void k_pw(
        const float* __restrict__ W, const float* __restrict__ bias,
        const __nv_bfloat16* __restrict__ Xh, const __nv_bfloat16* __restrict__ Xl,
        const float* __restrict__ addsrc, const float* __restrict__ encp,
        float* __restrict__ outf,
        __nv_bfloat16* __restrict__ outh, __nv_bfloat16* __restrict__ outl,
        int mode)
{
    const int b  = blockIdx.z;
    const int t0 = blockIdx.x * 128;
    const int o0 = blockIdx.y * 64;
    const size_t bbase = (size_t)b*NCH*LFP;

    __shared__ __align__(16) __nv_bfloat16 Ah[64][40];
    __shared__ __align__(16) __nv_bfloat16 Al[64][40];
    __shared__ __align__(16) __nv_bfloat16 Bh[32][136];
    __shared__ __align__(16) __nv_bfloat16 Bl[32][136];

    const int tid  = threadIdx.x;
    const int lane = tid & 31, warp = tid >> 5;
    const int wm = warp & 1, wn = warp >> 1;

    const int ar = tid >> 2, ac = (tid & 3) << 3;
    const int br = tid >> 3, bc = (tid & 7) << 3;

    float aR[8];
    uint4 bh0, bh1, bl0, bl1;
    {
        const float* wp = &W[(size_t)(o0 + ar)*NCH + ac];
        *(float4*)&aR[0] = *(const float4*)&wp[0];
        *(float4*)&aR[4] = *(const float4*)&wp[4];
        size_t xoff = bbase + (size_t)br*LFP + t0 + bc;
        bh0 = *(const uint4*)&Xh[xoff];
        bh1 = *(const uint4*)&Xh[xoff + 64];
        bl0 = *(const uint4*)&Xl[xoff];
        bl1 = *(const uint4*)&Xl[xoff + 64];
    }

    float acc[2][4][4];
    #pragma unroll
    for (int i = 0; i < 2; i++)
        #pragma unroll
        for (int j = 0; j < 4; j++)
            #pragma unroll
            for (int r = 0; r < 4; r++) acc[i][j][r] = 0.f;

    #pragma unroll 1
    for (int kt = 0; kt < 8; kt++) {
        splitStore8(aR, &Ah[ar][ac], &Al[ar][ac]);
        *(uint4*)&Bh[br][bc]      = bh0;
        *(uint4*)&Bh[br][bc + 64] = bh1;
        *(uint4*)&Bl[br][bc]      = bl0;
        *(uint4*)&Bl[br][bc + 64] = bl1;
        __syncthreads();
        if (kt < 7) {
            int k0 = (kt + 1) * 32;
            const float* wp = &W[(size_t)(o0 + ar)*NCH + k0 + ac];
            *(float4*)&aR[0] = *(const float4*)&wp[0];
            *(float4*)&aR[4] = *(const float4*)&wp[4];
            size_t xoff = bbase + (size_t)(k0 + br)*LFP + t0 + bc;
            bh0 = *(const uint4*)&Xh[xoff];
            bh1 = *(const uint4*)&Xh[xoff + 64];
            bl0 = *(const uint4*)&Xl[xoff];
            bl1 = *(const uint4*)&Xl[xoff + 64];
        }
        #pragma unroll
        for (int ks = 0; ks < 2; ks++) {
            const int kb = ks * 16;
            unsigned a_hi[2][4], a_lo[2][4], b_hi[2][4], b_lo[2][4];
            #pragma unroll
            for (int mt = 0; mt < 2; mt++) {
                int rowA = wm*32 + mt*16 + (lane & 15);
                int colA = kb + ((lane >> 4) << 3);
                unsigned sa = (unsigned)__cvta_generic_to_shared(&Ah[rowA][colA]);
                LDSM4(a_hi[mt], sa);
                unsigned sl = (unsigned)__cvta_generic_to_shared(&Al[rowA][colA]);
                LDSM4(a_lo[mt], sl);
            }
            #pragma unroll
            for (int ng = 0; ng < 2; ng++) {
                int rowB = kb + (lane & 15);
                int colB = wn*32 + ng*16 + ((lane >> 4) << 3);
                unsigned sb = (unsigned)__cvta_generic_to_shared(&Bh[rowB][colB]);
                LDSM4T(b_hi[ng], sb);
                unsigned sl = (unsigned)__cvta_generic_to_shared(&Bl[rowB][colB]);
                LDSM4T(b_lo[ng], sl);
            }
            #pragma unroll
            for (int mt = 0; mt < 2; mt++)
                #pragma unroll
                for (int ng = 0; ng < 2; ng++)
                    #pragma unroll
                    for (int hf = 0; hf < 2; hf++) {
                        int nt = ng*2 + hf;
                        MMA_BF16(acc[mt][nt], a_hi[mt], b_hi[ng][hf*2], b_hi[ng][hf*2+1]);
                        MMA_BF16(acc[mt][nt], a_hi[mt], b_lo[ng][hf*2], b_lo[ng][hf*2+1]);
                        MMA_BF16(acc[mt][nt], a_lo[mt], b_hi[ng][hf*2], b_hi[ng][hf*2+1]);
                    }
        }
        __syncthreads();
    }

    const int g8 = lane >> 2, tq = lane & 3;
    #pragma unroll
    for (int mt = 0; mt < 2; mt++)
        #pragma unroll
        for (int rr = 0; rr < 2; rr++) {
            int o = o0 + wm*32 + mt*16 + rr*8 + g8;
            float bv = bias[o];
            size_t rowo = bbase + (size_t)o*LFP;
            #pragma unroll
            for (int nt = 0; nt < 4; nt++) {
                int t = t0 + wn*32 + nt*8 + tq*2;
                float v0 = acc[mt][nt][rr*2+0] + bv;
                float v1 = acc[mt][nt][rr*2+1] + bv;
                if (mode == 1 || mode == 3) {
                    float2 ad = *(const float2*)&addsrc[rowo + t];
                    v0 += ad.x; v1 += ad.y;
                } else if (mode == 2) {
                    float2 e = *(const float2*)&encp[rowo + t];
                    v0 = fmaxf(v0, 0.f) * e.x;
                    v1 = fmaxf(v1, 0.f) * e.y;
                }
                if (t     >= LF) v0 = 0.f;
                if (t + 1 >= LF) v1 = 0.f;
                if (mode == 3) {
                    __nv_bfloat16 h0, l0, h1, l1;
                    split1(v0, h0, l0); split1(v1, h1, l1);
                    *(__nv_bfloat162*)&outh[rowo + t] = __nv_bfloat162(h0, h1);
                    *(__nv_bfloat162*)&outl[rowo + t] = __nv_bfloat162(l0, l1);
                } else {
                    *(float2*)&outf[rowo + t] = make_float2(v0, v1);
                }
            }
        }
}

// ---------------- fused block chain: prelu -> LN -> 3x(involution + prelu) --------
// lane = frame (32 frames: 26 interior + 3 halo each side); warp = 32-channel strip.
// m lives in 32 registers/thread; temporal neighbors via shfl; kergen via partials.
__global__ __launch_bounds__(256) void k_invchain(
    const float* __restrict__ x,
    const float* __restrict__ lng, const float* __restrict__ lnb,
    const float* __restrict__ alphaScalar,
    const float* __restrict__ prelu_a,      // [3*NCH] for this block
    int bp0,
    __nv_bfloat16* __restrict__ xnh, __nv_bfloat16* __restrict__ xnl,
    float* __restrict__ mout)
{
    __shared__ float w_s[3][3][NCH];
    __shared__ float al_s[3][NCH];
    __shared__ float gs[NCH], bs[NCH];
    __shared__ float lnp[8][2][32];
    __shared__ float part[2][8][3][32];
    __shared__ float bc_s[9];

    const int b    = blockIdx.y;
    const int t0   = blockIdx.x * TILE_INT;
    const int tid  = threadIdx.x;
    const int lane = tid & 31, warp = tid >> 5;
    const int c0   = warp * 32;
    const int tg   = t0 - 3 + lane;
    const bool inseq = (tg >= 0 && tg < LF);
    const bool interior = (lane >= 3 && lane < 3 + TILE_INT) && (tg < LFP);
    const size_t bbase = (size_t)b*NCH*LFP;
    const float aS = *alphaScalar;

    // preload all constants (covered by first barrier)
    for (int i = tid; i < 9*NCH; i += 256) (&w_s[0][0][0])[i] = g_wc[(size_t)bp0*3*NCH + i];
    for (int i = tid; i < 3*NCH; i += 256) (&al_s[0][0])[i] = prelu_a[i];
    if (tid < NCH) { gs[tid] = lng[tid]; bs[tid] = lnb[tid]; }
    if (tid < 9)   bc_s[tid] = g_bcol[bp0*3 + tid];

    // P0: load + scalar prelu + LN partials (m in registers)
    float m[32];
    float s = 0.f, q = 0.f;
    {
        const float* xp = x + bbase + (size_t)c0*LFP + tg;
        #pragma unroll
        for (int i = 0; i < 32; i++) {
            float v = 0.f;
            if (inseq) v = xp[(size_t)i*LFP];
            v = (v >= 0.f) ? v : aS*v;
            m[i] = v; s += v; q += v*v;
        }
    }
    lnp[warp][0][lane] = s; lnp[warp][1][lane] = q;
    __syncthreads();

    float mu, rs;
    {
        float S = 0.f, Q = 0.f;
        #pragma unroll
        for (int w = 0; w < 8; w++) { S += lnp[w][0][lane]; Q += lnp[w][1][lane]; }
        mu = S * (1.f/NCH);
        rs = rsqrtf(Q * (1.f/NCH) - mu*mu + EPSF);
    }

    // P2: normalize + mask + xn split-store + step-0 kergen partials
    {
        float p0 = 0.f, p1 = 0.f, p2 = 0.f;
        #pragma unroll
        for (int i = 0; i < 32; i++) {
            int c = c0 + i;
            float v = (m[i] - mu)*rs*gs[c] + bs[c];
            if (!inseq) v = 0.f;
            m[i] = v;
            p0 = fmaf(w_s[0][0][c], v, p0);
            p1 = fmaf(w_s[0][1][c], v, p1);
            p2 = fmaf(w_s[0][2][c], v, p2);
            if (interior) {
                __nv_bfloat16 h, l; split1(v, h, l);
                size_t gi = bbase + (size_t)c*LFP + tg;
                xnh[gi] = h; xnl[gi] = l;
            }
        }
        part[0][warp][0][lane] = p0;
        part[0][warp][1][lane] = p1;
        part[0][warp][2][lane] = p2;
    }
    __syncthreads();

    float k0 = bc_s[0], k1 = bc_s[1], k2 = bc_s[2];
    #pragma unroll
    for (int w = 0; w < 8; w++) {
        k0 += part[0][w][0][lane];
        k1 += part[0][w][1][lane];
        k2 += part[0][w][2][lane];
    }

    // P3: three involution steps (apply fused with next-step kergen partials)
    #pragma unroll
    for (int st = 0; st < 3; st++) {
        float np0 = 0.f, np1 = 0.f, np2 = 0.f;
        #pragma unroll
        for (int i = 0; i < 32; i++) {
            int c = c0 + i;
            float v  = m[i];
            float vm = __shfl_up_sync(0xffffffffu, v, 1);
            float vp = __shfl_down_sync(0xffffffffu, v, 1);
            float o = k1 * v;
            o = fmaf(k0, vm, o);
            o = fmaf(k2, vp, o);
            float al = al_s[st][c];
            o = (o >= 0.f) ? o : al*o;
            if (!inseq) o = 0.f;
            m[i] = o;
            if (st < 2) {
                np0 = fmaf(w_s[st+1][0][c], o, np0);
                np1 = fmaf(w_s[st+1][1][c], o, np1);
                np2 = fmaf(w_s[st+1][2][c], o, np2);
            } else if (interior) {
                mout[bbase + (size_t)c*LFP + tg] = o;
            }
        }
        if (st < 2) {
            int pb = (st + 1) & 1;
            part[pb][warp][0][lane] = np0;
            part[pb][warp][1][lane] = np1;
            part[pb][warp][2][lane] = np2;
            __syncthreads();
            k0 = bc_s[(st+1)*3 + 0]; k1 = bc_s[(st+1)*3 + 1]; k2 = bc_s[(st+1)*3 + 2];
            #pragma unroll
            for (int w = 0; w < 8; w++) {
                k0 += part[pb][w][0][lane];
                k1 += part[pb][w][1][lane];
                k2 += part[pb][w][2][lane];
            }
        }
    }
}

// ---------------- decoder ----------------
__global__ __launch_bounds__(256) void k_dpart(const float* __restrict__ masked,
                                               const float* __restrict__ dw)
{
    __shared__ float sw[NCH*16];
    for (int i = threadIdx.x; i < NCH*16; i += 256) sw[i] = dw[i];
    __syncthreads();
    int b = blockIdx.y;
    int t = blockIdx.x*256 + threadIdx.x;
    float acc[16];
    #pragma unroll
    for (int l = 0; l < 16; l++) acc[l] = 0.f;
    const float* mb = masked + (size_t)b*NCH*LFP + t;
    #pragma unroll 8
    for (int c = 0; c < NCH; c++) {
        float v = mb[(size_t)c*LFP];
        #pragma unroll
        for (int l = 0; l < 16; l++) acc[l] += v * sw[c*16 + l];
    }
    bool pad = (t >= LF);
    #pragma unroll
    for (int l = 0; l < 16; l++)
        g_part[((size_t)b*16 + l)*LFP + t] = pad ? 0.f : acc[l];
}

__global__ void k_combine(float* __restrict__ outp)
{
    int b = blockIdx.y;
    int s = blockIdx.x*256 + threadIdx.x;
    int t0 = s >> 3, l = s & 7;
    float v = g_part[((size_t)b*16 + l)*LFP + t0];
    if (t0 >= 1) v += g_part[((size_t)b*16 + l + 8)*LFP + t0 - 1];
    outp[(size_t)b*SEQLEN + s] = v;
}

// ---------------- driver ----------------
extern "C" void kernel_launch(void* const* d_in, const int* in_sizes, int n_in,
                              void* d_out, int out_size)
{
    (void)in_sizes; (void)n_in; (void)out_size;
    const float* noisy_ac    = (const float*)d_in[0];
    const float* noisy_bc    = (const float*)d_in[1];
    const float* ac_w        = (const float*)d_in[2];
    const float* bc_w        = (const float*)d_in[3];
    const float* me_ln_g     = (const float*)d_in[4];
    const float* me_ln_b     = (const float*)d_in[5];
    const float* me_init_w   = (const float*)d_in[6];
    const float* me_init_b   = (const float*)d_in[7];
    const float* blk_ln_g    = (const float*)d_in[8];
    const float* blk_ln_b    = (const float*)d_in[9];
    const float* blk_act_a   = (const float*)d_in[10];
    const float* inv_w1      = (const float*)d_in[11];
    const float* inv_b1      = (const float*)d_in[12];
    const float* inv_w2      = (const float*)d_in[13];
    const float* inv_b2      = (const float*)d_in[14];
    const float* inv_prelu_a = (const float*)d_in[15];
    const float* skip_w      = (const float*)d_in[16];
    const float* skip_b      = (const float*)d_in[17];
    const float* me_final_w  = (const float*)d_in[18];
    const float* me_final_b  = (const float*)d_in[19];
    const float* dec_w       = (const float*)d_in[20];
    float* out = (float*)d_out;

    float *p_enc, *p_x, *p_m1, *p_msk;
    __nv_bfloat16 *p_xnh, *p_xnl, *p_x3h, *p_x3l;
    cudaGetSymbolAddress((void**)&p_enc, g_enc);
    cudaGetSymbolAddress((void**)&p_x,   g_x);
    cudaGetSymbolAddress((void**)&p_m1,  g_m1);
    cudaGetSymbolAddress((void**)&p_msk, g_msk);
    cudaGetSymbolAddress((void**)&p_xnh, g_xnh);
    cudaGetSymbolAddress((void**)&p_xnl, g_xnl);
    cudaGetSymbolAddress((void**)&p_x3h, g_x3h);
    cudaGetSymbolAddress((void**)&p_x3l, g_x3l);

    dim3 pwGrid(32, 4, NB);
    const int invGridX = (LF + TILE_INT - 1) / TILE_INT;   // 158

    k_prep  <<<dim3(12, 3), 256>>>(inv_w1, inv_b1, inv_w2, inv_b2);
    k_enc_ln<<<dim3(128, NB), dim3(32, 8)>>>(noisy_ac, noisy_bc, ac_w, bc_w,
                                             me_ln_g, me_ln_b, p_enc, p_xnh, p_xnl);
    k_pw<<<pwGrid, 256>>>(me_init_w, me_init_b, p_xnh, p_xnl,
                          nullptr, nullptr, p_x, nullptr, nullptr, 0);

    for (int blk = 0; blk < 4; blk++) {
        k_invchain<<<dim3(invGridX, NB), 256>>>(
            p_x, blk_ln_g + blk*NCH, blk_ln_b + blk*NCH,
            blk_act_a + blk, inv_prelu_a + (size_t)blk*3*NCH, blk*3,
            p_xnh, p_xnl, p_m1);
        if (blk < 3)
            k_pw<<<pwGrid, 256>>>(skip_w + (size_t)blk*NCH*NCH, skip_b + blk*NCH,
                                  p_xnh, p_xnl, p_m1, nullptr,
                                  p_x, nullptr, nullptr, 1);
        else
            k_pw<<<pwGrid, 256>>>(skip_w + (size_t)blk*NCH*NCH, skip_b + blk*NCH,
                                  p_xnh, p_xnl, p_m1, nullptr,
                                  nullptr, p_x3h, p_x3l, 3);
    }

    k_pw<<<pwGrid, 256>>>(me_final_w, me_final_b, p_x3h, p_x3l,
                          nullptr, p_enc, p_msk, nullptr, nullptr, 2);
    k_dpart  <<<dim3(16, NB), 256>>>(p_msk, dec_w);
    k_combine<<<dim3(128, NB), 256>>>(out);
}

// round 5
// speedup vs baseline: 3.1897x; 1.0059x over previous
#include <cuda_runtime.h>
#include <cuda_bf16.h>
#include <stdint.h>

#define LF     4095
#define LFP    4096
#define NCH    256
#define NB     4
#define SEQLEN 32768
#define EPSF   1e-5f
#define TILE_INT 26

// ---------------- scratch (static device globals; no allocation) ----------------
__device__ float g_enc [NB*NCH*LFP];
__device__ float g_x   [NB*NCH*LFP];
__device__ float g_m1  [NB*NCH*LFP];
__device__ float g_msk [NB*NCH*LFP];
__device__ __nv_bfloat16 g_xnh[NB*NCH*LFP];
__device__ __nv_bfloat16 g_xnl[NB*NCH*LFP];
__device__ __nv_bfloat16 g_x3h[NB*NCH*LFP];
__device__ __nv_bfloat16 g_x3l[NB*NCH*LFP];
__device__ float g_part[NB*16*LFP];
__device__ float g_wc  [12*3*NCH];
__device__ float g_bcol[12*3];
__device__ __nv_bfloat16 g_wh[6*NCH*NCH];   // pre-split GEMM weights (hi)
__device__ __nv_bfloat16 g_wl[6*NCH*NCH];   // (lo)

__device__ __forceinline__ void split1(float x, __nv_bfloat16& h, __nv_bfloat16& l)
{
    h = __float2bfloat16(x);
    l = __float2bfloat16(x - __bfloat162float(h));
}

// ---------------- collapse w2@w1 (+ bias) per (block,p,j) ----------------
__global__ void k_prep(const float* __restrict__ w1, const float* __restrict__ b1,
                       const float* __restrict__ w2, const float* __restrict__ b2)
{
    int bp = blockIdx.x;
    int j  = blockIdx.y;
    int c  = threadIdx.x;
    const float* w1p = w1 + (size_t)bp*64*NCH;
    const float* w2p = w2 + ((size_t)bp*3 + j)*64;
    float acc = 0.f;
    #pragma unroll 8
    for (int cr = 0; cr < 64; cr++) acc += w2p[cr] * w1p[(size_t)cr*NCH + c];
    g_wc[((size_t)bp*3 + j)*NCH + c] = acc;
    if (c == 0) {
        const float* b1p = b1 + bp*64;
        float bb = b2[bp*3 + j];
        for (int cr = 0; cr < 64; cr++) bb += w2p[cr]*b1p[cr];
        g_bcol[bp*3 + j] = bb;
    }
}

// ---------------- split 6 weight matrices into bf16 hi/lo ----------------
__global__ void k_wsplit(const float* __restrict__ mi, const float* __restrict__ sk,
                         const float* __restrict__ mf)
{
    int slot = blockIdx.y;
    int idx  = blockIdx.x*256 + threadIdx.x;      // 0..65535
    const float* src = (slot == 0) ? mi : (slot <= 4 ? sk + (size_t)(slot-1)*NCH*NCH : mf);
    float v = src[idx];
    __nv_bfloat16 h, l; split1(v, h, l);
    g_wh[(size_t)slot*NCH*NCH + idx] = h;
    g_wl[(size_t)slot*NCH*NCH + idx] = l;
}

// ---------------- encoder + fused channel-LN ----------------
__global__ void k_enc_ln(const float* __restrict__ ac, const float* __restrict__ bc,
                         const float* __restrict__ acw, const float* __restrict__ bcw,
                         const float* __restrict__ lng, const float* __restrict__ lnb,
                         float* __restrict__ enc,
                         __nv_bfloat16* __restrict__ xnh, __nv_bfloat16* __restrict__ xnl)
{
    int b  = blockIdx.y;
    int t0 = blockIdx.x * 32;
    int tx = threadIdx.x, ty = threadIdx.y;
    __shared__ float sa[264], sb[264];
    __shared__ float ss[8][33], sq[8][33];
    int tid  = ty*32 + tx;
    int base = t0 * 8;
    for (int i = tid; i < 264; i += 256) {
        int gi = base + i;
        sa[i] = (gi < SEQLEN) ? ac[(size_t)b*SEQLEN + gi] : 0.f;
        sb[i] = (gi < SEQLEN) ? bc[(size_t)b*SEQLEN + gi] : 0.f;
    }
    __syncthreads();
    int t = t0 + tx;
    bool valid = (t < LF);
    const size_t bbase = (size_t)b*NCH*LFP;
    float vals[32];
    float s = 0.f, q = 0.f;
    #pragma unroll
    for (int i = 0; i < 32; i++) {
        int n = ty + i*8;
        float acc = 0.f;
        #pragma unroll
        for (int l = 0; l < 16; l++)
            acc += sa[tx*8 + l]*acw[n*16 + l] + sb[tx*8 + l]*bcw[n*16 + l];
        if (!valid) acc = 0.f;
        vals[i] = acc; s += acc; q += acc*acc;
        enc[bbase + (size_t)n*LFP + t] = acc;
    }
    ss[ty][tx] = s; sq[ty][tx] = q;
    __syncthreads();
    if (ty == 0) {
        float S = 0.f, Q = 0.f;
        #pragma unroll
        for (int j = 0; j < 8; j++) { S += ss[j][tx]; Q += sq[j][tx]; }
        float mu  = S * (1.f/NCH);
        float var = Q * (1.f/NCH) - mu*mu;
        ss[0][tx] = mu;
        sq[0][tx] = rsqrtf(var + EPSF);
    }
    __syncthreads();
    float mu = ss[0][tx], rs = sq[0][tx];
    #pragma unroll
    for (int i = 0; i < 32; i++) {
        int c = ty + i*8;
        float v = valid ? (vals[i] - mu)*rs*lng[c] + lnb[c] : 0.f;
        __nv_bfloat16 h, l; split1(v, h, l);
        size_t gi = bbase + (size_t)c*LFP + t;
        xnh[gi] = h; xnl[gi] = l;
    }
}

// ---------------- tensor-core pointwise GEMM (cp.async double-buffered) ---------
#define LDSM4(R, addr)  asm volatile("ldmatrix.sync.aligned.m8n8.x4.shared.b16 {%0,%1,%2,%3}, [%4];" \
    : "=r"(R[0]),"=r"(R[1]),"=r"(R[2]),"=r"(R[3]) : "r"(addr))
#define LDSM4T(R, addr) asm volatile("ldmatrix.sync.aligned.m8n8.x4.trans.shared.b16 {%0,%1,%2,%3}, [%4];" \
    : "=r"(R[0]),"=r"(R[1]),"=r"(R[2]),"=r"(R[3]) : "r"(addr))
#define MMA_BF16(D, A, B0, B1) asm volatile( \
    "mma.sync.aligned.m16n8k16.row.col.f32.bf16.bf16.f32 " \
    "{%0,%1,%2,%3}, {%4,%5,%6,%7}, {%8,%9}, {%0,%1,%2,%3};" \
    : "+f"(D[0]), "+f"(D[1]), "+f"(D[2]), "+f"(D[3]) \
    : "r"(A[0]), "r"(A[1]), "r"(A[2]), "r"(A[3]), "r"(B0), "r"(B1))
#define CP16(dst, src) asm volatile("cp.async.cg.shared.global [%0], [%1], 16;" \
    :: "r"(dst), "l"(src))
#define CP_COMMIT()   asm volatile("cp.async.commit_group;")
#define CP_WAIT(n)    asm volatile("cp.async.wait_group %0;" :: "n"(n))

// dynamic smem layout (elements of bf16):
//   Ah[2][64][40]  : off 0      (2*2560)
//   Al[2][64][40]  : off 5120
//   Bh[2][32][136] : off 10240  (2*4352)
//   Bl[2][32][136] : off 18944
#define PW_SMEM_ELEMS 27648
#define AH_OFF(s)  ((s)*2560)
#define AL_OFF(s)  (5120 + (s)*2560)
#define BH_OFF(s)  (10240 + (s)*4352)
#define BL_OFF(s)  (18944 + (s)*4352)

__global__ __launch_bounds__(256, 2) void k_pw(
        int wslot, const float* __restrict__ bias,
        const __nv_bfloat16* __restrict__ Xh, const __nv_bfloat16* __restrict__ Xl,
        const float* __restrict__ addsrc, const float* __restrict__ encp,
        float* __restrict__ outf,
        __nv_bfloat16* __restrict__ outh, __nv_bfloat16* __restrict__ outl,
        int mode)
{
    extern __shared__ __nv_bfloat16 smp[];
    const int b  = blockIdx.z;
    const int t0 = blockIdx.x * 128;
    const int o0 = blockIdx.y * 64;
    const size_t bbase = (size_t)b*NCH*LFP;

    const __nv_bfloat16* Wh = g_wh + (size_t)wslot*NCH*NCH;
    const __nv_bfloat16* Wl = g_wl + (size_t)wslot*NCH*NCH;

    const int tid  = threadIdx.x;
    const int lane = tid & 31, warp = tid >> 5;
    const int wm = warp & 1, wn = warp >> 1;

    const int ar = tid >> 2, ac = (tid & 3) << 3;   // A: 64 rows x 32 cols, 8 el/thread
    const int br = tid >> 3, bc = (tid & 7) << 4;   // B: 32 rows x 128 cols, 16 el/thread

    const unsigned smBase = (unsigned)__cvta_generic_to_shared(smp);

    // prefetch k-tile kt into stage s
    auto prefetch = [&](int s, int kt) {
        int k0 = kt * 32;
        CP16(smBase + (AH_OFF(s) + ar*40 + ac)*2, &Wh[(size_t)(o0 + ar)*NCH + k0 + ac]);
        CP16(smBase + (AL_OFF(s) + ar*40 + ac)*2, &Wl[(size_t)(o0 + ar)*NCH + k0 + ac]);
        size_t xo = bbase + (size_t)(k0 + br)*LFP + t0 + bc;
        CP16(smBase + (BH_OFF(s) + br*136 + bc)*2,     &Xh[xo]);
        CP16(smBase + (BH_OFF(s) + br*136 + bc + 8)*2, &Xh[xo + 8]);
        CP16(smBase + (BL_OFF(s) + br*136 + bc)*2,     &Xl[xo]);
        CP16(smBase + (BL_OFF(s) + br*136 + bc + 8)*2, &Xl[xo + 8]);
    };

    float acc[2][4][4];
    #pragma unroll
    for (int i = 0; i < 2; i++)
        #pragma unroll
        for (int j = 0; j < 4; j++)
            #pragma unroll
            for (int r = 0; r < 4; r++) acc[i][j][r] = 0.f;

    prefetch(0, 0);
    CP_COMMIT();

    #pragma unroll 1
    for (int kt = 0; kt < 8; kt++) {
        const int cur = kt & 1;
        if (kt < 7) { prefetch(cur ^ 1, kt + 1); CP_COMMIT(); CP_WAIT(1); }
        else        { CP_WAIT(0); }
        __syncthreads();

        #pragma unroll
        for (int ks = 0; ks < 2; ks++) {
            const int kb = ks * 16;
            unsigned a_hi[2][4], a_lo[2][4], b_hi[2][4], b_lo[2][4];
            #pragma unroll
            for (int mt = 0; mt < 2; mt++) {
                int rowA = wm*32 + mt*16 + (lane & 15);
                int colA = kb + ((lane >> 4) << 3);
                unsigned off = (AH_OFF(cur) + rowA*40 + colA)*2;
                LDSM4(a_hi[mt], smBase + off);
                off = (AL_OFF(cur) + rowA*40 + colA)*2;
                LDSM4(a_lo[mt], smBase + off);
            }
            #pragma unroll
            for (int ng = 0; ng < 2; ng++) {
                int rowB = kb + (lane & 15);
                int colB = wn*32 + ng*16 + ((lane >> 4) << 3);
                unsigned off = (BH_OFF(cur) + rowB*136 + colB)*2;
                LDSM4T(b_hi[ng], smBase + off);
                off = (BL_OFF(cur) + rowB*136 + colB)*2;
                LDSM4T(b_lo[ng], smBase + off);
            }
            #pragma unroll
            for (int mt = 0; mt < 2; mt++)
                #pragma unroll
                for (int ng = 0; ng < 2; ng++)
                    #pragma unroll
                    for (int hf = 0; hf < 2; hf++) {
                        int nt = ng*2 + hf;
                        MMA_BF16(acc[mt][nt], a_hi[mt], b_hi[ng][hf*2], b_hi[ng][hf*2+1]);
                        MMA_BF16(acc[mt][nt], a_hi[mt], b_lo[ng][hf*2], b_lo[ng][hf*2+1]);
                        MMA_BF16(acc[mt][nt], a_lo[mt], b_hi[ng][hf*2], b_hi[ng][hf*2+1]);
                    }
        }
        __syncthreads();
    }

    const int g8 = lane >> 2, tq = lane & 3;
    #pragma unroll
    for (int mt = 0; mt < 2; mt++)
        #pragma unroll
        for (int rr = 0; rr < 2; rr++) {
            int o = o0 + wm*32 + mt*16 + rr*8 + g8;
            float bv = bias[o];
            size_t rowo = bbase + (size_t)o*LFP;
            #pragma unroll
            for (int nt = 0; nt < 4; nt++) {
                int t = t0 + wn*32 + nt*8 + tq*2;
                float v0 = acc[mt][nt][rr*2+0] + bv;
                float v1 = acc[mt][nt][rr*2+1] + bv;
                if (mode == 1 || mode == 3) {
                    float2 ad = *(const float2*)&addsrc[rowo + t];
                    v0 += ad.x; v1 += ad.y;
                } else if (mode == 2) {
                    float2 e = *(const float2*)&encp[rowo + t];
                    v0 = fmaxf(v0, 0.f) * e.x;
                    v1 = fmaxf(v1, 0.f) * e.y;
                }
                if (t     >= LF) v0 = 0.f;
                if (t + 1 >= LF) v1 = 0.f;
                if (mode == 3) {
                    __nv_bfloat16 h0, l0, h1, l1;
                    split1(v0, h0, l0); split1(v1, h1, l1);
                    *(__nv_bfloat162*)&outh[rowo + t] = __nv_bfloat162(h0, h1);
                    *(__nv_bfloat162*)&outl[rowo + t] = __nv_bfloat162(l0, l1);
                } else {
                    *(float2*)&outf[rowo + t] = make_float2(v0, v1);
                }
            }
        }
}

// ---------------- fused block chain: prelu -> LN -> 3x(involution + prelu) --------
__global__ __launch_bounds__(256) void k_invchain(
    const float* __restrict__ x,
    const float* __restrict__ lng, const float* __restrict__ lnb,
    const float* __restrict__ alphaScalar,
    const float* __restrict__ prelu_a,
    int bp0,
    __nv_bfloat16* __restrict__ xnh, __nv_bfloat16* __restrict__ xnl,
    float* __restrict__ mout)
{
    __shared__ float w_s[3][3][NCH];
    __shared__ float al_s[3][NCH];
    __shared__ float gs[NCH], bs[NCH];
    __shared__ float lnp[8][2][32];
    __shared__ float part[2][8][3][32];
    __shared__ float bc_s[9];

    const int b    = blockIdx.y;
    const int t0   = blockIdx.x * TILE_INT;
    const int tid  = threadIdx.x;
    const int lane = tid & 31, warp = tid >> 5;
    const int c0   = warp * 32;
    const int tg   = t0 - 3 + lane;
    const bool inseq = (tg >= 0 && tg < LF);
    const bool interior = (lane >= 3 && lane < 3 + TILE_INT) && (tg < LFP);
    const size_t bbase = (size_t)b*NCH*LFP;
    const float aS = *alphaScalar;

    for (int i = tid; i < 9*NCH; i += 256) (&w_s[0][0][0])[i] = g_wc[(size_t)bp0*3*NCH + i];
    for (int i = tid; i < 3*NCH; i += 256) (&al_s[0][0])[i] = prelu_a[i];
    if (tid < NCH) { gs[tid] = lng[tid]; bs[tid] = lnb[tid]; }
    if (tid < 9)   bc_s[tid] = g_bcol[bp0*3 + tid];

    float m[32];
    float s = 0.f, q = 0.f;
    {
        const float* xp = x + bbase + (size_t)c0*LFP + tg;
        #pragma unroll
        for (int i = 0; i < 32; i++) {
            float v = 0.f;
            if (inseq) v = xp[(size_t)i*LFP];
            v = (v >= 0.f) ? v : aS*v;
            m[i] = v; s += v; q += v*v;
        }
    }
    lnp[warp][0][lane] = s; lnp[warp][1][lane] = q;
    __syncthreads();

    float mu, rs;
    {
        float S = 0.f, Q = 0.f;
        #pragma unroll
        for (int w = 0; w < 8; w++) { S += lnp[w][0][lane]; Q += lnp[w][1][lane]; }
        mu = S * (1.f/NCH);
        rs = rsqrtf(Q * (1.f/NCH) - mu*mu + EPSF);
    }

    {
        float p0 = 0.f, p1 = 0.f, p2 = 0.f;
        #pragma unroll
        for (int i = 0; i < 32; i++) {
            int c = c0 + i;
            float v = (m[i] - mu)*rs*gs[c] + bs[c];
            if (!inseq) v = 0.f;
            m[i] = v;
            p0 = fmaf(w_s[0][0][c], v, p0);
            p1 = fmaf(w_s[0][1][c], v, p1);
            p2 = fmaf(w_s[0][2][c], v, p2);
            if (interior) {
                __nv_bfloat16 h, l; split1(v, h, l);
                size_t gi = bbase + (size_t)c*LFP + tg;
                xnh[gi] = h; xnl[gi] = l;
            }
        }
        part[0][warp][0][lane] = p0;
        part[0][warp][1][lane] = p1;
        part[0][warp][2][lane] = p2;
    }
    __syncthreads();

    float k0 = bc_s[0], k1 = bc_s[1], k2 = bc_s[2];
    #pragma unroll
    for (int w = 0; w < 8; w++) {
        k0 += part[0][w][0][lane];
        k1 += part[0][w][1][lane];
        k2 += part[0][w][2][lane];
    }

    #pragma unroll
    for (int st = 0; st < 3; st++) {
        float np0 = 0.f, np1 = 0.f, np2 = 0.f;
        #pragma unroll
        for (int i = 0; i < 32; i++) {
            int c = c0 + i;
            float v  = m[i];
            float vm = __shfl_up_sync(0xffffffffu, v, 1);
            float vp = __shfl_down_sync(0xffffffffu, v, 1);
            float o = k1 * v;
            o = fmaf(k0, vm, o);
            o = fmaf(k2, vp, o);
            float al = al_s[st][c];
            o = (o >= 0.f) ? o : al*o;
            if (!inseq) o = 0.f;
            m[i] = o;
            if (st < 2) {
                np0 = fmaf(w_s[st+1][0][c], o, np0);
                np1 = fmaf(w_s[st+1][1][c], o, np1);
                np2 = fmaf(w_s[st+1][2][c], o, np2);
            } else if (interior) {
                mout[bbase + (size_t)c*LFP + tg] = o;
            }
        }
        if (st < 2) {
            int pb = (st + 1) & 1;
            part[pb][warp][0][lane] = np0;
            part[pb][warp][1][lane] = np1;
            part[pb][warp][2][lane] = np2;
            __syncthreads();
            k0 = bc_s[(st+1)*3 + 0]; k1 = bc_s[(st+1)*3 + 1]; k2 = bc_s[(st+1)*3 + 2];
            #pragma unroll
            for (int w = 0; w < 8; w++) {
                k0 += part[pb][w][0][lane];
                k1 += part[pb][w][1][lane];
                k2 += part[pb][w][2][lane];
            }
        }
    }
}

// ---------------- decoder ----------------
__global__ __launch_bounds__(256) void k_dpart(const float* __restrict__ masked,
                                               const float* __restrict__ dw)
{
    __shared__ float sw[NCH*16];
    for (int i = threadIdx.x; i < NCH*16; i += 256) sw[i] = dw[i];
    __syncthreads();
    int b = blockIdx.y;
    int t = blockIdx.x*256 + threadIdx.x;
    float acc[16];
    #pragma unroll
    for (int l = 0; l < 16; l++) acc[l] = 0.f;
    const float* mb = masked + (size_t)b*NCH*LFP + t;
    #pragma unroll 8
    for (int c = 0; c < NCH; c++) {
        float v = mb[(size_t)c*LFP];
        #pragma unroll
        for (int l = 0; l < 16; l++) acc[l] += v * sw[c*16 + l];
    }
    bool pad = (t >= LF);
    #pragma unroll
    for (int l = 0; l < 16; l++)
        g_part[((size_t)b*16 + l)*LFP + t] = pad ? 0.f : acc[l];
}

__global__ void k_combine(float* __restrict__ outp)
{
    int b = blockIdx.y;
    int s = blockIdx.x*256 + threadIdx.x;
    int t0 = s >> 3, l = s & 7;
    float v = g_part[((size_t)b*16 + l)*LFP + t0];
    if (t0 >= 1) v += g_part[((size_t)b*16 + l + 8)*LFP + t0 - 1];
    outp[(size_t)b*SEQLEN + s] = v;
}

// ---------------- driver ----------------
extern "C" void kernel_launch(void* const* d_in, const int* in_sizes, int n_in,
                              void* d_out, int out_size)
{
    (void)in_sizes; (void)n_in; (void)out_size;
    const float* noisy_ac    = (const float*)d_in[0];
    const float* noisy_bc    = (const float*)d_in[1];
    const float* ac_w        = (const float*)d_in[2];
    const float* bc_w        = (const float*)d_in[3];
    const float* me_ln_g     = (const float*)d_in[4];
    const float* me_ln_b     = (const float*)d_in[5];
    const float* me_init_w   = (const float*)d_in[6];
    const float* me_init_b   = (const float*)d_in[7];
    const float* blk_ln_g    = (const float*)d_in[8];
    const float* blk_ln_b    = (const float*)d_in[9];
    const float* blk_act_a   = (const float*)d_in[10];
    const float* inv_w1      = (const float*)d_in[11];
    const float* inv_b1      = (const float*)d_in[12];
    const float* inv_w2      = (const float*)d_in[13];
    const float* inv_b2      = (const float*)d_in[14];
    const float* inv_prelu_a = (const float*)d_in[15];
    const float* skip_w      = (const float*)d_in[16];
    const float* skip_b      = (const float*)d_in[17];
    const float* me_final_w  = (const float*)d_in[18];
    const float* me_final_b  = (const float*)d_in[19];
    const float* dec_w       = (const float*)d_in[20];
    float* out = (float*)d_out;

    float *p_enc, *p_x, *p_m1, *p_msk;
    __nv_bfloat16 *p_xnh, *p_xnl, *p_x3h, *p_x3l;
    cudaGetSymbolAddress((void**)&p_enc, g_enc);
    cudaGetSymbolAddress((void**)&p_x,   g_x);
    cudaGetSymbolAddress((void**)&p_m1,  g_m1);
    cudaGetSymbolAddress((void**)&p_msk, g_msk);
    cudaGetSymbolAddress((void**)&p_xnh, g_xnh);
    cudaGetSymbolAddress((void**)&p_xnl, g_xnl);
    cudaGetSymbolAddress((void**)&p_x3h, g_x3h);
    cudaGetSymbolAddress((void**)&p_x3l, g_x3l);

    const int pwSmem = PW_SMEM_ELEMS * (int)sizeof(__nv_bfloat16);   // 55296
    static int attrDone = 0;
    if (!attrDone) {
        cudaFuncSetAttribute(k_pw, cudaFuncAttributeMaxDynamicSharedMemorySize, pwSmem);
        attrDone = 1;
    }

    dim3 pwGrid(32, 4, NB);
    const int invGridX = (LF + TILE_INT - 1) / TILE_INT;

    k_prep  <<<dim3(12, 3), 256>>>(inv_w1, inv_b1, inv_w2, inv_b2);
    k_wsplit<<<dim3(256, 6), 256>>>(me_init_w, skip_w, me_final_w);
    k_enc_ln<<<dim3(128, NB), dim3(32, 8)>>>(noisy_ac, noisy_bc, ac_w, bc_w,
                                             me_ln_g, me_ln_b, p_enc, p_xnh, p_xnl);
    k_pw<<<pwGrid, 256, pwSmem>>>(0, me_init_b, p_xnh, p_xnl,
                                  nullptr, nullptr, p_x, nullptr, nullptr, 0);

    for (int blk = 0; blk < 4; blk++) {
        k_invchain<<<dim3(invGridX, NB), 256>>>(
            p_x, blk_ln_g + blk*NCH, blk_ln_b + blk*NCH,
            blk_act_a + blk, inv_prelu_a + (size_t)blk*3*NCH, blk*3,
            p_xnh, p_xnl, p_m1);
        if (blk < 3)
            k_pw<<<pwGrid, 256, pwSmem>>>(1 + blk, skip_b + blk*NCH,
                                          p_xnh, p_xnl, p_m1, nullptr,
                                          p_x, nullptr, nullptr, 1);
        else
            k_pw<<<pwGrid, 256, pwSmem>>>(1 + blk, skip_b + blk*NCH,
                                          p_xnh, p_xnl, p_m1, nullptr,
                                          nullptr, p_x3h, p_x3l, 3);
    }

    k_pw<<<pwGrid, 256, pwSmem>>>(5, me_final_b, p_x3h, p_x3l,
                                  nullptr, p_enc, p_msk, nullptr, nullptr, 2);
    k_dpart  <<<dim3(16, NB), 256>>>(p_msk, dec_w);
    k_combine<<<dim3(128, NB), 256>>>(out);
}